// round 2
// baseline (speedup 1.0000x reference)
#include <cuda_runtime.h>
#include <math.h>

#define B_ 4
#define T_ 2048
#define C_ 1024
#define H_ 16
#define D_ 64
#define M_ (B_ * T_)          // 8192 rows
#define HALF_ 32              // D/2 for RoPE

// ---------------- scratch (device globals: no runtime allocation) ----------
__device__ float g_q[(size_t)B_ * H_ * T_ * D_];   // [B,H,T,D]
__device__ float g_k[(size_t)B_ * H_ * T_ * D_];
__device__ float g_v[(size_t)B_ * H_ * T_ * D_];
__device__ float g_y[(size_t)M_ * C_];             // attention output [B,T,C]
__device__ float g_cos[T_ * HALF_];
__device__ float g_sin[T_ * HALF_];

// ---------------- RoPE table --------------------------------------------
__global__ void rope_init_kernel() {
    int idx = blockIdx.x * blockDim.x + threadIdx.x;
    if (idx >= T_ * HALF_) return;
    int t = idx / HALF_;
    int i = idx % HALF_;
    double alpha = pow(10000.0, -(double)i / (double)HALF_);
    double ang = (double)t * alpha;
    g_cos[idx] = (float)cos(ang);
    g_sin[idx] = (float)sin(ang);
}

// ---------------- fused QKV GEMM + bias + RoPE epilogue -------------------
// out[m,n] = sum_k x[m,k] * W[n,k] + bias[n];  z selects (q,k,v)
// Tile 64x64, BK=16, 256 threads, 4x4 microtile per thread.
__global__ __launch_bounds__(256) void qkv_gemm_kernel(
    const float* __restrict__ x,
    const float* __restrict__ wq, const float* __restrict__ bq,
    const float* __restrict__ wk, const float* __restrict__ bk,
    const float* __restrict__ wv, const float* __restrict__ bv)
{
    const int z = blockIdx.z;
    const float* W    = (z == 0) ? wq : (z == 1) ? wk : wv;
    const float* bias = (z == 0) ? bq : (z == 1) ? bk : bv;
    float* dst        = (z == 0) ? g_q : (z == 1) ? g_k : g_v;

    __shared__ float As[16][64];
    __shared__ float Bs[16][64];
    __shared__ float Cs[64][65];

    const int m0 = blockIdx.x * 64;
    const int h  = blockIdx.y;       // BN=64 == D, so one head per block col
    const int n0 = h * 64;
    const int tid = threadIdx.x;
    const int tx = tid & 15;
    const int ty = tid >> 4;

    const int lrow = tid >> 2;          // 0..63
    const int lcol = (tid & 3) * 4;     // 0,4,8,12

    float acc[4][4];
    #pragma unroll
    for (int i = 0; i < 4; i++)
        #pragma unroll
        for (int j = 0; j < 4; j++) acc[i][j] = 0.f;

    for (int k0 = 0; k0 < C_; k0 += 16) {
        float4 av = *(const float4*)&x[(size_t)(m0 + lrow) * C_ + k0 + lcol];
        float4 bv4 = *(const float4*)&W[(size_t)(n0 + lrow) * C_ + k0 + lcol];
        As[lcol + 0][lrow] = av.x; As[lcol + 1][lrow] = av.y;
        As[lcol + 2][lrow] = av.z; As[lcol + 3][lrow] = av.w;
        Bs[lcol + 0][lrow] = bv4.x; Bs[lcol + 1][lrow] = bv4.y;
        Bs[lcol + 2][lrow] = bv4.z; Bs[lcol + 3][lrow] = bv4.w;
        __syncthreads();
        #pragma unroll
        for (int kk = 0; kk < 16; kk++) {
            float a[4], b[4];
            #pragma unroll
            for (int i = 0; i < 4; i++) a[i] = As[kk][ty * 4 + i];
            #pragma unroll
            for (int j = 0; j < 4; j++) b[j] = Bs[kk][tx * 4 + j];
            #pragma unroll
            for (int i = 0; i < 4; i++)
                #pragma unroll
                for (int j = 0; j < 4; j++) acc[i][j] += a[i] * b[j];
        }
        __syncthreads();
    }

    // stage tile (with bias) to smem for the RoPE pairing
    #pragma unroll
    for (int i = 0; i < 4; i++)
        #pragma unroll
        for (int j = 0; j < 4; j++)
            Cs[ty * 4 + i][tx * 4 + j] = acc[i][j] + bias[n0 + tx * 4 + j];
    __syncthreads();

    const int b = m0 / T_;
    const int tbase = m0 % T_;
    float* hb = dst + ((size_t)(b * H_ + h) * T_) * D_;

    if (z < 2) {
        // RoPE: pairs (i, i+32)
        #pragma unroll
        for (int it = 0; it < 8; it++) {
            int p = tid + it * 256;          // 0..2047
            int row = p >> 5;
            int i = p & 31;
            int t = tbase + row;
            float xr = Cs[row][i];
            float xi = Cs[row][i + 32];
            float cs = g_cos[t * HALF_ + i];
            float sn = g_sin[t * HALF_ + i];
            float* o = hb + (size_t)t * D_;
            o[i]        = xr * cs - xi * sn;
            o[i + 32]   = xr * sn + xi * cs;
        }
    } else {
        #pragma unroll
        for (int it = 0; it < 16; it++) {
            int e = tid + it * 256;          // 0..4095
            int row = e >> 6;
            int d = e & 63;
            hb[(size_t)(tbase + row) * D_ + d] = Cs[row][d];
        }
    }
}

// ---------------- causal flash attention ----------------------------------
// grid (T/128, H, B), 128 threads; one query row per thread.
__global__ __launch_bounds__(128) void attn_kernel() {
    __shared__ float Ks[32][64];
    __shared__ float Vs[32][64];

    const int b = blockIdx.z;
    const int h = blockIdx.y;
    const int tq = blockIdx.x * 128 + threadIdx.x;

    const float* qp = g_q + ((size_t)(b * H_ + h) * T_ + tq) * D_;
    const float* kb = g_k + ((size_t)(b * H_ + h) * T_) * D_;
    const float* vb = g_v + ((size_t)(b * H_ + h) * T_) * D_;

    float q[64];
    #pragma unroll
    for (int d4 = 0; d4 < 16; d4++) {
        float4 v4 = *(const float4*)&qp[d4 * 4];
        q[d4 * 4 + 0] = v4.x; q[d4 * 4 + 1] = v4.y;
        q[d4 * 4 + 2] = v4.z; q[d4 * 4 + 3] = v4.w;
    }

    float acc[64];
    #pragma unroll
    for (int d = 0; d < 64; d++) acc[d] = 0.f;
    float mval = -INFINITY, l = 0.f;
    const float scale = 0.125f;   // 1/sqrt(64)

    const int ntiles = blockIdx.x * 4 + 4;   // keys up to block max tq
    for (int kt = 0; kt < ntiles; kt++) {
        __syncthreads();
        const float* kp = kb + (size_t)kt * 32 * 64;
        const float* vp = vb + (size_t)kt * 32 * 64;
        #pragma unroll
        for (int it = 0; it < 4; it++) {
            int idx = threadIdx.x + it * 128;    // 512 float4 per tile
            ((float4*)Ks)[idx] = ((const float4*)kp)[idx];
            ((float4*)Vs)[idx] = ((const float4*)vp)[idx];
        }
        __syncthreads();

        if (kt * 32 > tq) continue;   // fully masked for this row

        float s[32];
        #pragma unroll
        for (int j = 0; j < 32; j++) {
            float sum = 0.f;
            #pragma unroll
            for (int d4 = 0; d4 < 16; d4++) {
                float4 kv = ((const float4*)Ks[j])[d4];
                sum += q[d4 * 4 + 0] * kv.x;
                sum += q[d4 * 4 + 1] * kv.y;
                sum += q[d4 * 4 + 2] * kv.z;
                sum += q[d4 * 4 + 3] * kv.w;
            }
            int kidx = kt * 32 + j;
            s[j] = (kidx <= tq) ? sum * scale : -INFINITY;
        }

        float tm = s[0];
        #pragma unroll
        for (int j = 1; j < 32; j++) tm = fmaxf(tm, s[j]);
        float mn = fmaxf(mval, tm);
        float corr = __expf(mval - mn);
        l *= corr;
        #pragma unroll
        for (int d = 0; d < 64; d++) acc[d] *= corr;

        #pragma unroll
        for (int j = 0; j < 32; j++) {
            float p = __expf(s[j] - mn);
            l += p;
            #pragma unroll
            for (int d4 = 0; d4 < 16; d4++) {
                float4 vv = ((const float4*)Vs[j])[d4];
                acc[d4 * 4 + 0] += p * vv.x;
                acc[d4 * 4 + 1] += p * vv.y;
                acc[d4 * 4 + 2] += p * vv.z;
                acc[d4 * 4 + 3] += p * vv.w;
            }
        }
        mval = mn;
    }

    float inv = 1.f / l;
    float* o = g_y + ((size_t)b * T_ + tq) * C_ + h * D_;
    #pragma unroll
    for (int d4 = 0; d4 < 16; d4++) {
        float4 r;
        r.x = acc[d4 * 4 + 0] * inv;
        r.y = acc[d4 * 4 + 1] * inv;
        r.z = acc[d4 * 4 + 2] * inv;
        r.w = acc[d4 * 4 + 3] * inv;
        *(float4*)&o[d4 * 4] = r;
    }
}

// ---------------- output projection GEMM ---------------------------------
__global__ __launch_bounds__(256) void proj_gemm_kernel(
    const float* __restrict__ wp, const float* __restrict__ bp,
    float* __restrict__ out)
{
    __shared__ float As[16][64];
    __shared__ float Bs[16][64];

    const int m0 = blockIdx.x * 64;
    const int n0 = blockIdx.y * 64;
    const int tid = threadIdx.x;
    const int tx = tid & 15;
    const int ty = tid >> 4;
    const int lrow = tid >> 2;
    const int lcol = (tid & 3) * 4;

    float acc[4][4];
    #pragma unroll
    for (int i = 0; i < 4; i++)
        #pragma unroll
        for (int j = 0; j < 4; j++) acc[i][j] = 0.f;

    for (int k0 = 0; k0 < C_; k0 += 16) {
        float4 av = *(const float4*)&g_y[(size_t)(m0 + lrow) * C_ + k0 + lcol];
        float4 bv4 = *(const float4*)&wp[(size_t)(n0 + lrow) * C_ + k0 + lcol];
        As[lcol + 0][lrow] = av.x; As[lcol + 1][lrow] = av.y;
        As[lcol + 2][lrow] = av.z; As[lcol + 3][lrow] = av.w;
        Bs[lcol + 0][lrow] = bv4.x; Bs[lcol + 1][lrow] = bv4.y;
        Bs[lcol + 2][lrow] = bv4.z; Bs[lcol + 3][lrow] = bv4.w;
        __syncthreads();
        #pragma unroll
        for (int kk = 0; kk < 16; kk++) {
            float a[4], b[4];
            #pragma unroll
            for (int i = 0; i < 4; i++) a[i] = As[kk][ty * 4 + i];
            #pragma unroll
            for (int j = 0; j < 4; j++) b[j] = Bs[kk][tx * 4 + j];
            #pragma unroll
            for (int i = 0; i < 4; i++)
                #pragma unroll
                for (int j = 0; j < 4; j++) acc[i][j] += a[i] * b[j];
        }
        __syncthreads();
    }

    #pragma unroll
    for (int i = 0; i < 4; i++) {
        float4 r;
        r.x = acc[i][0] + bp[n0 + tx * 4 + 0];
        r.y = acc[i][1] + bp[n0 + tx * 4 + 1];
        r.z = acc[i][2] + bp[n0 + tx * 4 + 2];
        r.w = acc[i][3] + bp[n0 + tx * 4 + 3];
        *(float4*)&out[(size_t)(m0 + ty * 4 + i) * C_ + n0 + tx * 4] = r;
    }
}

// ---------------- launch ---------------------------------------------------
extern "C" void kernel_launch(void* const* d_in, const int* in_sizes, int n_in,
                              void* d_out, int out_size)
{
    const float* x  = (const float*)d_in[0];
    const float* wq = (const float*)d_in[1];
    const float* bq = (const float*)d_in[2];
    const float* wk = (const float*)d_in[3];
    const float* bk = (const float*)d_in[4];
    const float* wv = (const float*)d_in[5];
    const float* bv = (const float*)d_in[6];
    const float* wp = (const float*)d_in[7];
    const float* bp = (const float*)d_in[8];
    float* out = (float*)d_out;

    rope_init_kernel<<<(T_ * HALF_ + 255) / 256, 256>>>();
    qkv_gemm_kernel<<<dim3(M_ / 64, H_, 3), 256>>>(x, wq, bq, wk, bk, wv, bv);
    attn_kernel<<<dim3(T_ / 128, H_, B_), 128>>>();
    proj_gemm_kernel<<<dim3(M_ / 64, C_ / 64), 256>>>(wp, bp, out);
}

// round 4
// speedup vs baseline: 1.4148x; 1.4148x over previous
#include <cuda_runtime.h>
#include <cuda_bf16.h>
#include <math.h>
#include <stdint.h>

#define B_ 4
#define T_ 2048
#define C_ 1024
#define H_ 16
#define D_ 64
#define M_ (B_ * T_)          // 8192 rows
#define HALF_ 32              // D/2 for RoPE
#define NCHUNK_ (C_ / 64)     // 16 K-chunks of 64 bf16

// ---------------- scratch (device globals: no runtime allocation) ----------
__device__ float g_q[(size_t)B_ * H_ * T_ * D_];   // [B,H,T,D] fp32
__device__ float g_k[(size_t)B_ * H_ * T_ * D_];
__device__ float g_v[(size_t)B_ * H_ * T_ * D_];
__device__ float g_cos[T_ * HALF_];
__device__ float g_sin[T_ * HALF_];
__device__ __nv_bfloat16 g_xhi[(size_t)M_ * C_];
__device__ __nv_bfloat16 g_xlo[(size_t)M_ * C_];
__device__ __nv_bfloat16 g_whi[(size_t)4 * C_ * C_];   // wq,wk,wv,wp
__device__ __nv_bfloat16 g_wlo[(size_t)4 * C_ * C_];
__device__ __nv_bfloat16 g_yhi[(size_t)M_ * C_];
__device__ __nv_bfloat16 g_ylo[(size_t)M_ * C_];

// ---------------- PTX helpers (portable: sm_80+ features only) -------------
__device__ __forceinline__ uint32_t smem_u32(const void* p) {
    uint32_t a;
    asm("{ .reg .u64 t; cvta.to.shared.u64 t, %1; cvt.u32.u64 %0, t; }"
        : "=r"(a) : "l"(p));
    return a;
}

__device__ __forceinline__ void ldsm_x4(uint32_t addr, uint32_t* r) {
    asm volatile("ldmatrix.sync.aligned.m8n8.x4.shared.b16 {%0,%1,%2,%3}, [%4];"
        : "=r"(r[0]), "=r"(r[1]), "=r"(r[2]), "=r"(r[3]) : "r"(addr));
}

__device__ __forceinline__ void mma16816(float* d, const uint32_t* a, const uint32_t* b) {
    asm volatile(
        "mma.sync.aligned.m16n8k16.row.col.f32.bf16.bf16.f32 "
        "{%0,%1,%2,%3}, {%4,%5,%6,%7}, {%8,%9}, {%0,%1,%2,%3};"
        : "+f"(d[0]), "+f"(d[1]), "+f"(d[2]), "+f"(d[3])
        : "r"(a[0]), "r"(a[1]), "r"(a[2]), "r"(a[3]), "r"(b[0]), "r"(b[1]));
}

// ---------------- smem layout ----------------------------------------------
#define S_AHI 0
#define S_ALO 16384
#define S_BHI 32768
#define S_BLO 49152
#define CS_LD 132
#define SMEM_BYTES (128 * CS_LD * 4)    // 67584 (also covers the 64KB stage)

// ---------------- RoPE table -----------------------------------------------
__global__ void rope_init_kernel() {
    int idx = blockIdx.x * blockDim.x + threadIdx.x;
    if (idx >= T_ * HALF_) return;
    int t = idx / HALF_;
    int i = idx % HALF_;
    double alpha = pow(10000.0, -(double)i / (double)HALF_);
    double ang = (double)t * alpha;
    g_cos[idx] = (float)cos(ang);
    g_sin[idx] = (float)sin(ang);
}

// ---------------- fp32 -> bf16 hi/lo split ---------------------------------
__global__ __launch_bounds__(256) void split_kernel(
    const float* __restrict__ src, __nv_bfloat16* __restrict__ hi,
    __nv_bfloat16* __restrict__ lo, int n4)
{
    int i = blockIdx.x * blockDim.x + threadIdx.x;
    if (i >= n4) return;
    float4 v = ((const float4*)src)[i];
    __nv_bfloat16 h0 = __float2bfloat16(v.x);
    __nv_bfloat16 h1 = __float2bfloat16(v.y);
    __nv_bfloat16 h2 = __float2bfloat16(v.z);
    __nv_bfloat16 h3 = __float2bfloat16(v.w);
    __nv_bfloat16 l0 = __float2bfloat16(v.x - __bfloat162float(h0));
    __nv_bfloat16 l1 = __float2bfloat16(v.y - __bfloat162float(h1));
    __nv_bfloat16 l2 = __float2bfloat16(v.z - __bfloat162float(h2));
    __nv_bfloat16 l3 = __float2bfloat16(v.w - __bfloat162float(h3));
    __nv_bfloat162* H = (__nv_bfloat162*)hi;
    __nv_bfloat162* L = (__nv_bfloat162*)lo;
    H[2 * i + 0] = __halves2bfloat162(h0, h1);
    H[2 * i + 1] = __halves2bfloat162(h2, h3);
    L[2 * i + 0] = __halves2bfloat162(l0, l1);
    L[2 * i + 1] = __halves2bfloat162(l2, l3);
}

// ---------------- mma.sync GEMM mainloop -----------------------------------
// acc[mi][nj][e]: warp (wm,wn) computes C[m0+wm*64 .. +64, n0+wn*32 .. +32]
__device__ __forceinline__ void gemm_mma(
    const __nv_bfloat16* __restrict__ Ahi, const __nv_bfloat16* __restrict__ Alo,
    const __nv_bfloat16* __restrict__ Bhi, const __nv_bfloat16* __restrict__ Blo,
    int m0, int n0, char* smem, float acc[4][4][4])
{
    const int tid = threadIdx.x;
    const int wid = tid >> 5;
    const int lane = tid & 31;
    const int wm = wid >> 2;        // 0..1
    const int wn = wid & 3;         // 0..3
    const uint32_t sbase = smem_u32(smem);

    #pragma unroll
    for (int mi = 0; mi < 4; mi++)
        #pragma unroll
        for (int nj = 0; nj < 4; nj++)
            #pragma unroll
            for (int e = 0; e < 4; e++) acc[mi][nj][e] = 0.f;

    // ldmatrix per-lane row/col assignments
    const int a_row = lane & 15;          // row within 16-row m-tile
    const int a_kh  = lane >> 4;          // which 16B k-half
    const int bg    = lane >> 3;          // B address group 0..3
    const int b_row = ((bg >> 1) << 3) + (lane & 7);  // n row within 16
    const int b_kh  = bg & 1;

    for (int kc = 0; kc < NCHUNK_; kc++) {
        const int k0 = kc * 64;
        #pragma unroll
        for (int it = 0; it < 4; it++) {
            int idx = tid + it * 256;       // 0..1023 16B chunks
            int r = idx >> 3;
            int cb = idx & 7;
            uint32_t off = (uint32_t)(r * 128 + cb * 16);
            uint32_t sw = off ^ (uint32_t)((r & 7) << 4);
            const size_t ga = (size_t)(m0 + r) * C_ + k0 + cb * 8;
            const size_t gb = (size_t)(n0 + r) * C_ + k0 + cb * 8;
            *(uint4*)(smem + S_AHI + sw) = *(const uint4*)(Ahi + ga);
            *(uint4*)(smem + S_ALO + sw) = *(const uint4*)(Alo + ga);
            *(uint4*)(smem + S_BHI + sw) = *(const uint4*)(Bhi + gb);
            *(uint4*)(smem + S_BLO + sw) = *(const uint4*)(Blo + gb);
        }
        __syncthreads();

        #pragma unroll
        for (int kk = 0; kk < 4; kk++) {
            // B fragments for this warp's 32-wide n range (4 n8 blocks)
            uint32_t bh[4][2], bl[4][2];
            #pragma unroll
            for (int np = 0; np < 2; np++) {
                int R = wn * 32 + np * 16 + b_row;
                int cb = kk * 2 + b_kh;
                uint32_t off = (uint32_t)(R * 128 + cb * 16);
                uint32_t sw = off ^ (uint32_t)((R & 7) << 4);
                ldsm_x4(sbase + S_BHI + sw, &bh[np * 2][0]);
                ldsm_x4(sbase + S_BLO + sw, &bl[np * 2][0]);
            }
            #pragma unroll
            for (int mi = 0; mi < 4; mi++) {
                uint32_t ah[4], al[4];
                int R = wm * 64 + mi * 16 + a_row;
                int cb = kk * 2 + a_kh;
                uint32_t off = (uint32_t)(R * 128 + cb * 16);
                uint32_t sw = off ^ (uint32_t)((R & 7) << 4);
                ldsm_x4(sbase + S_AHI + sw, ah);
                ldsm_x4(sbase + S_ALO + sw, al);
                #pragma unroll
                for (int nj = 0; nj < 4; nj++) {
                    mma16816(acc[mi][nj], ah, bh[nj]);
                    mma16816(acc[mi][nj], ah, bl[nj]);
                    mma16816(acc[mi][nj], al, bh[nj]);
                }
            }
        }
        __syncthreads();
    }
}

// store accumulators (+bias) into smem fp32 tile Cs[128][CS_LD]
__device__ __forceinline__ void acc_to_smem(
    float acc[4][4][4], char* smem, const float* __restrict__ bias, int n0)
{
    float* Cs = (float*)smem;
    const int wid = threadIdx.x >> 5;
    const int lane = threadIdx.x & 31;
    const int wm = wid >> 2, wn = wid & 3;
    const int r0 = wm * 64 + (lane >> 2);
    const int c0 = wn * 32 + 2 * (lane & 3);
    #pragma unroll
    for (int mi = 0; mi < 4; mi++) {
        #pragma unroll
        for (int nj = 0; nj < 4; nj++) {
            int r = r0 + mi * 16;
            int c = c0 + nj * 8;
            float b0 = __ldg(&bias[n0 + c]);
            float b1 = __ldg(&bias[n0 + c + 1]);
            Cs[r * CS_LD + c]           = acc[mi][nj][0] + b0;
            Cs[r * CS_LD + c + 1]       = acc[mi][nj][1] + b1;
            Cs[(r + 8) * CS_LD + c]     = acc[mi][nj][2] + b0;
            Cs[(r + 8) * CS_LD + c + 1] = acc[mi][nj][3] + b1;
        }
    }
}

// ---------------- QKV GEMM + bias + RoPE epilogue --------------------------
__global__ __launch_bounds__(256) void qkv_mma_kernel(
    const float* __restrict__ bq, const float* __restrict__ bk,
    const float* __restrict__ bv)
{
    extern __shared__ __align__(16) char smem[];
    const int z = blockIdx.z;
    const __nv_bfloat16* Whi = g_whi + (size_t)z * C_ * C_;
    const __nv_bfloat16* Wlo = g_wlo + (size_t)z * C_ * C_;
    const float* bias = (z == 0) ? bq : (z == 1) ? bk : bv;
    float* dst = (z == 0) ? g_q : (z == 1) ? g_k : g_v;

    const int m0 = blockIdx.x * 128;
    const int n0 = blockIdx.y * 128;

    float acc[4][4][4];
    gemm_mma(g_xhi, g_xlo, Whi, Wlo, m0, n0, smem, acc);
    acc_to_smem(acc, smem, bias, n0);
    __syncthreads();

    const float* Cs = (const float*)smem;
    const int tid = threadIdx.x;
    const int b = m0 / T_;
    const int tbase = m0 % T_;

    if (z < 2) {
        // 128 rows x 2 heads x 32 RoPE pairs = 8192 pairs
        #pragma unroll
        for (int it = 0; it < 32; it++) {
            int p = tid + it * 256;
            int row = p >> 6;
            int q6 = p & 63;
            int hd = q6 >> 5;
            int i = q6 & 31;
            int t = tbase + row;
            int h = (n0 >> 6) + hd;
            float xr = Cs[row * CS_LD + hd * 64 + i];
            float xi = Cs[row * CS_LD + hd * 64 + i + 32];
            float cs = g_cos[t * HALF_ + i];
            float sn = g_sin[t * HALF_ + i];
            float* o = dst + ((size_t)(b * H_ + h) * T_ + t) * D_;
            o[i]      = xr * cs - xi * sn;
            o[i + 32] = xr * sn + xi * cs;
        }
    } else {
        #pragma unroll
        for (int it = 0; it < 16; it++) {
            int e = tid + it * 256;          // float4 id 0..4095
            int row = e >> 5;
            int col = (e & 31) * 4;
            int hd = col >> 6;
            int d = col & 63;
            int t = tbase + row;
            int h = (n0 >> 6) + hd;
            float4 v4 = *(const float4*)&Cs[row * CS_LD + col];
            *(float4*)&dst[((size_t)(b * H_ + h) * T_ + t) * D_ + d] = v4;
        }
    }
}

// ---------------- output projection GEMM -----------------------------------
__global__ __launch_bounds__(256) void proj_mma_kernel(
    const float* __restrict__ bp, float* __restrict__ out)
{
    extern __shared__ __align__(16) char smem[];
    const int m0 = blockIdx.x * 128;
    const int n0 = blockIdx.y * 128;
    const __nv_bfloat16* Whi = g_whi + (size_t)3 * C_ * C_;
    const __nv_bfloat16* Wlo = g_wlo + (size_t)3 * C_ * C_;

    float acc[4][4][4];
    gemm_mma(g_yhi, g_ylo, Whi, Wlo, m0, n0, smem, acc);
    acc_to_smem(acc, smem, bp, n0);
    __syncthreads();

    const float* Cs = (const float*)smem;
    const int tid = threadIdx.x;
    #pragma unroll
    for (int it = 0; it < 16; it++) {
        int e = tid + it * 256;
        int row = e >> 5;
        int col = (e & 31) * 4;
        float4 v4 = *(const float4*)&Cs[row * CS_LD + col];
        *(float4*)&out[(size_t)(m0 + row) * C_ + n0 + col] = v4;
    }
}

// ---------------- causal flash attention (fp32, unchanged math) ------------
__global__ __launch_bounds__(128) void attn_kernel() {
    __shared__ float Ks[32][64];
    __shared__ float Vs[32][64];

    const int b = blockIdx.z;
    const int h = blockIdx.y;
    const int tq = blockIdx.x * 128 + threadIdx.x;

    const float* qp = g_q + ((size_t)(b * H_ + h) * T_ + tq) * D_;
    const float* kb = g_k + ((size_t)(b * H_ + h) * T_) * D_;
    const float* vb = g_v + ((size_t)(b * H_ + h) * T_) * D_;

    float q[64];
    #pragma unroll
    for (int d4 = 0; d4 < 16; d4++) {
        float4 v4 = *(const float4*)&qp[d4 * 4];
        q[d4 * 4 + 0] = v4.x; q[d4 * 4 + 1] = v4.y;
        q[d4 * 4 + 2] = v4.z; q[d4 * 4 + 3] = v4.w;
    }

    float acc[64];
    #pragma unroll
    for (int d = 0; d < 64; d++) acc[d] = 0.f;
    float mval = -INFINITY, l = 0.f;
    const float scale = 0.125f;

    const int ntiles = blockIdx.x * 4 + 4;
    for (int kt = 0; kt < ntiles; kt++) {
        __syncthreads();
        const float* kp = kb + (size_t)kt * 32 * 64;
        const float* vp = vb + (size_t)kt * 32 * 64;
        #pragma unroll
        for (int it = 0; it < 4; it++) {
            int idx = threadIdx.x + it * 128;
            ((float4*)Ks)[idx] = ((const float4*)kp)[idx];
            ((float4*)Vs)[idx] = ((const float4*)vp)[idx];
        }
        __syncthreads();

        if (kt * 32 > tq) continue;

        float s[32];
        #pragma unroll
        for (int j = 0; j < 32; j++) {
            float sum = 0.f;
            #pragma unroll
            for (int d4 = 0; d4 < 16; d4++) {
                float4 kv = ((const float4*)Ks[j])[d4];
                sum += q[d4 * 4 + 0] * kv.x;
                sum += q[d4 * 4 + 1] * kv.y;
                sum += q[d4 * 4 + 2] * kv.z;
                sum += q[d4 * 4 + 3] * kv.w;
            }
            int kidx = kt * 32 + j;
            s[j] = (kidx <= tq) ? sum * scale : -INFINITY;
        }

        float tm = s[0];
        #pragma unroll
        for (int j = 1; j < 32; j++) tm = fmaxf(tm, s[j]);
        float mn = fmaxf(mval, tm);
        float corr = __expf(mval - mn);
        l *= corr;
        #pragma unroll
        for (int d = 0; d < 64; d++) acc[d] *= corr;

        #pragma unroll
        for (int j = 0; j < 32; j++) {
            float p = __expf(s[j] - mn);
            l += p;
            #pragma unroll
            for (int d4 = 0; d4 < 16; d4++) {
                float4 vv = ((const float4*)Vs[j])[d4];
                acc[d4 * 4 + 0] += p * vv.x;
                acc[d4 * 4 + 1] += p * vv.y;
                acc[d4 * 4 + 2] += p * vv.z;
                acc[d4 * 4 + 3] += p * vv.w;
            }
        }
        mval = mn;
    }

    float inv = 1.f / l;
    size_t base = ((size_t)b * T_ + tq) * C_ + h * D_;
    __nv_bfloat162* Yh = (__nv_bfloat162*)(g_yhi + base);
    __nv_bfloat162* Yl = (__nv_bfloat162*)(g_ylo + base);
    #pragma unroll
    for (int d2 = 0; d2 < 32; d2++) {
        float v0 = acc[2 * d2 + 0] * inv;
        float v1 = acc[2 * d2 + 1] * inv;
        __nv_bfloat16 h0 = __float2bfloat16(v0);
        __nv_bfloat16 h1 = __float2bfloat16(v1);
        __nv_bfloat16 l0 = __float2bfloat16(v0 - __bfloat162float(h0));
        __nv_bfloat16 l1 = __float2bfloat16(v1 - __bfloat162float(h1));
        Yh[d2] = __halves2bfloat162(h0, h1);
        Yl[d2] = __halves2bfloat162(l0, l1);
    }
}

// ---------------- launch ---------------------------------------------------
extern "C" void kernel_launch(void* const* d_in, const int* in_sizes, int n_in,
                              void* d_out, int out_size)
{
    const float* x  = (const float*)d_in[0];
    const float* wq = (const float*)d_in[1];
    const float* bq = (const float*)d_in[2];
    const float* wk = (const float*)d_in[3];
    const float* bk = (const float*)d_in[4];
    const float* wv = (const float*)d_in[5];
    const float* bv = (const float*)d_in[6];
    const float* wp = (const float*)d_in[7];
    const float* bp = (const float*)d_in[8];
    float* out = (float*)d_out;

    static bool attr_done = false;
    if (!attr_done) {
        cudaFuncSetAttribute(qkv_mma_kernel,
                             cudaFuncAttributeMaxDynamicSharedMemorySize, SMEM_BYTES);
        cudaFuncSetAttribute(proj_mma_kernel,
                             cudaFuncAttributeMaxDynamicSharedMemorySize, SMEM_BYTES);
        attr_done = true;
    }

    __nv_bfloat16 *p_xhi, *p_xlo, *p_whi, *p_wlo;
    cudaGetSymbolAddress((void**)&p_xhi, g_xhi);
    cudaGetSymbolAddress((void**)&p_xlo, g_xlo);
    cudaGetSymbolAddress((void**)&p_whi, g_whi);
    cudaGetSymbolAddress((void**)&p_wlo, g_wlo);

    rope_init_kernel<<<(T_ * HALF_ + 255) / 256, 256>>>();

    split_kernel<<<(M_ * C_ / 4 + 255) / 256, 256>>>(x, p_xhi, p_xlo, M_ * C_ / 4);
    split_kernel<<<(C_ * C_ / 4 + 255) / 256, 256>>>(wq, p_whi + 0 * (size_t)C_ * C_,
                                                     p_wlo + 0 * (size_t)C_ * C_, C_ * C_ / 4);
    split_kernel<<<(C_ * C_ / 4 + 255) / 256, 256>>>(wk, p_whi + 1 * (size_t)C_ * C_,
                                                     p_wlo + 1 * (size_t)C_ * C_, C_ * C_ / 4);
    split_kernel<<<(C_ * C_ / 4 + 255) / 256, 256>>>(wv, p_whi + 2 * (size_t)C_ * C_,
                                                     p_wlo + 2 * (size_t)C_ * C_, C_ * C_ / 4);
    split_kernel<<<(C_ * C_ / 4 + 255) / 256, 256>>>(wp, p_whi + 3 * (size_t)C_ * C_,
                                                     p_wlo + 3 * (size_t)C_ * C_, C_ * C_ / 4);

    qkv_mma_kernel<<<dim3(M_ / 128, C_ / 128, 3), 256, SMEM_BYTES>>>(bq, bk, bv);
    attn_kernel<<<dim3(T_ / 128, H_, B_), 128>>>();
    proj_mma_kernel<<<dim3(M_ / 128, C_ / 128), 256, SMEM_BYTES>>>(bp, out);
}

// round 5
// speedup vs baseline: 3.5826x; 2.5323x over previous
#include <cuda_runtime.h>
#include <cuda_bf16.h>
#include <math.h>
#include <stdint.h>

#define B_ 4
#define T_ 2048
#define C_ 1024
#define H_ 16
#define D_ 64
#define M_ (B_ * T_)          // 8192 rows
#define HALF_ 32              // D/2 for RoPE
#define NCHUNK_ (C_ / 64)     // 16 K-chunks of 64 bf16

// ---------------- scratch (device globals: no runtime allocation) ----------
__device__ float g_cos[T_ * HALF_];
__device__ float g_sin[T_ * HALF_];
__device__ __nv_bfloat16 g_xhi[(size_t)M_ * C_];
__device__ __nv_bfloat16 g_xlo[(size_t)M_ * C_];
__device__ __nv_bfloat16 g_whi[(size_t)4 * C_ * C_];   // wq,wk,wv,wp
__device__ __nv_bfloat16 g_wlo[(size_t)4 * C_ * C_];
__device__ __nv_bfloat16 g_yhi[(size_t)M_ * C_];
__device__ __nv_bfloat16 g_ylo[(size_t)M_ * C_];
// Q,K (post-RoPE) and V as bf16 hi/lo, layout [B,H,T,D]
__device__ __nv_bfloat16 g_qhi[(size_t)B_ * H_ * T_ * D_];
__device__ __nv_bfloat16 g_qlo[(size_t)B_ * H_ * T_ * D_];
__device__ __nv_bfloat16 g_khi[(size_t)B_ * H_ * T_ * D_];
__device__ __nv_bfloat16 g_klo[(size_t)B_ * H_ * T_ * D_];
__device__ __nv_bfloat16 g_vhi[(size_t)B_ * H_ * T_ * D_];
__device__ __nv_bfloat16 g_vlo[(size_t)B_ * H_ * T_ * D_];

// ---------------- PTX helpers (portable: sm_80+ features only) -------------
__device__ __forceinline__ uint32_t smem_u32(const void* p) {
    uint32_t a;
    asm("{ .reg .u64 t; cvta.to.shared.u64 t, %1; cvt.u32.u64 %0, t; }"
        : "=r"(a) : "l"(p));
    return a;
}

__device__ __forceinline__ void ldsm_x4(uint32_t addr, uint32_t* r) {
    asm volatile("ldmatrix.sync.aligned.m8n8.x4.shared.b16 {%0,%1,%2,%3}, [%4];"
        : "=r"(r[0]), "=r"(r[1]), "=r"(r[2]), "=r"(r[3]) : "r"(addr));
}

__device__ __forceinline__ void ldsm_x4_trans(uint32_t addr, uint32_t* r) {
    asm volatile("ldmatrix.sync.aligned.m8n8.x4.trans.shared.b16 {%0,%1,%2,%3}, [%4];"
        : "=r"(r[0]), "=r"(r[1]), "=r"(r[2]), "=r"(r[3]) : "r"(addr));
}

__device__ __forceinline__ void mma16816(float* d, const uint32_t* a, const uint32_t* b) {
    asm volatile(
        "mma.sync.aligned.m16n8k16.row.col.f32.bf16.bf16.f32 "
        "{%0,%1,%2,%3}, {%4,%5,%6,%7}, {%8,%9}, {%0,%1,%2,%3};"
        : "+f"(d[0]), "+f"(d[1]), "+f"(d[2]), "+f"(d[3])
        : "r"(a[0]), "r"(a[1]), "r"(a[2]), "r"(a[3]), "r"(b[0]), "r"(b[1]));
}

__device__ __forceinline__ void split2(float a, float b, uint32_t& hi, uint32_t& lo) {
    __nv_bfloat16 h0 = __float2bfloat16(a);
    __nv_bfloat16 h1 = __float2bfloat16(b);
    __nv_bfloat16 l0 = __float2bfloat16(a - __bfloat162float(h0));
    __nv_bfloat16 l1 = __float2bfloat16(b - __bfloat162float(h1));
    __nv_bfloat162 H = __halves2bfloat162(h0, h1);
    __nv_bfloat162 L = __halves2bfloat162(l0, l1);
    hi = *(uint32_t*)&H;
    lo = *(uint32_t*)&L;
}

// ---------------- smem layout (GEMM) ---------------------------------------
#define S_AHI 0
#define S_ALO 16384
#define S_BHI 32768
#define S_BLO 49152
#define CS_LD 132
#define SMEM_BYTES (128 * CS_LD * 4)    // 67584

// ---------------- RoPE table -----------------------------------------------
__global__ void rope_init_kernel() {
    int idx = blockIdx.x * blockDim.x + threadIdx.x;
    if (idx >= T_ * HALF_) return;
    int t = idx / HALF_;
    int i = idx % HALF_;
    double alpha = pow(10000.0, -(double)i / (double)HALF_);
    double ang = (double)t * alpha;
    g_cos[idx] = (float)cos(ang);
    g_sin[idx] = (float)sin(ang);
}

// ---------------- fp32 -> bf16 hi/lo split ---------------------------------
__global__ __launch_bounds__(256) void split_kernel(
    const float* __restrict__ src, __nv_bfloat16* __restrict__ hi,
    __nv_bfloat16* __restrict__ lo, int n4)
{
    int i = blockIdx.x * blockDim.x + threadIdx.x;
    if (i >= n4) return;
    float4 v = ((const float4*)src)[i];
    uint32_t h0, l0, h1, l1;
    split2(v.x, v.y, h0, l0);
    split2(v.z, v.w, h1, l1);
    ((uint32_t*)hi)[2 * i + 0] = h0;
    ((uint32_t*)hi)[2 * i + 1] = h1;
    ((uint32_t*)lo)[2 * i + 0] = l0;
    ((uint32_t*)lo)[2 * i + 1] = l1;
}

// ---------------- mma.sync GEMM mainloop -----------------------------------
__device__ __forceinline__ void gemm_mma(
    const __nv_bfloat16* __restrict__ Ahi, const __nv_bfloat16* __restrict__ Alo,
    const __nv_bfloat16* __restrict__ Bhi, const __nv_bfloat16* __restrict__ Blo,
    int m0, int n0, char* smem, float acc[4][4][4])
{
    const int tid = threadIdx.x;
    const int wid = tid >> 5;
    const int lane = tid & 31;
    const int wm = wid >> 2;
    const int wn = wid & 3;
    const uint32_t sbase = smem_u32(smem);

    #pragma unroll
    for (int mi = 0; mi < 4; mi++)
        #pragma unroll
        for (int nj = 0; nj < 4; nj++)
            #pragma unroll
            for (int e = 0; e < 4; e++) acc[mi][nj][e] = 0.f;

    const int a_row = lane & 15;
    const int a_kh  = lane >> 4;
    const int bg    = lane >> 3;
    const int b_row = ((bg >> 1) << 3) + (lane & 7);
    const int b_kh  = bg & 1;

    for (int kc = 0; kc < NCHUNK_; kc++) {
        const int k0 = kc * 64;
        #pragma unroll
        for (int it = 0; it < 4; it++) {
            int idx = tid + it * 256;
            int r = idx >> 3;
            int cb = idx & 7;
            uint32_t off = (uint32_t)(r * 128 + cb * 16);
            uint32_t sw = off ^ (uint32_t)((r & 7) << 4);
            const size_t ga = (size_t)(m0 + r) * C_ + k0 + cb * 8;
            const size_t gb = (size_t)(n0 + r) * C_ + k0 + cb * 8;
            *(uint4*)(smem + S_AHI + sw) = *(const uint4*)(Ahi + ga);
            *(uint4*)(smem + S_ALO + sw) = *(const uint4*)(Alo + ga);
            *(uint4*)(smem + S_BHI + sw) = *(const uint4*)(Bhi + gb);
            *(uint4*)(smem + S_BLO + sw) = *(const uint4*)(Blo + gb);
        }
        __syncthreads();

        #pragma unroll
        for (int kk = 0; kk < 4; kk++) {
            uint32_t bh[4][2], bl[4][2];
            #pragma unroll
            for (int np = 0; np < 2; np++) {
                int R = wn * 32 + np * 16 + b_row;
                int cb = kk * 2 + b_kh;
                uint32_t off = (uint32_t)(R * 128 + cb * 16);
                uint32_t sw = off ^ (uint32_t)((R & 7) << 4);
                ldsm_x4(sbase + S_BHI + sw, &bh[np * 2][0]);
                ldsm_x4(sbase + S_BLO + sw, &bl[np * 2][0]);
            }
            #pragma unroll
            for (int mi = 0; mi < 4; mi++) {
                uint32_t ah[4], al[4];
                int R = wm * 64 + mi * 16 + a_row;
                int cb = kk * 2 + a_kh;
                uint32_t off = (uint32_t)(R * 128 + cb * 16);
                uint32_t sw = off ^ (uint32_t)((R & 7) << 4);
                ldsm_x4(sbase + S_AHI + sw, ah);
                ldsm_x4(sbase + S_ALO + sw, al);
                #pragma unroll
                for (int nj = 0; nj < 4; nj++) {
                    mma16816(acc[mi][nj], ah, bh[nj]);
                    mma16816(acc[mi][nj], ah, bl[nj]);
                    mma16816(acc[mi][nj], al, bh[nj]);
                }
            }
        }
        __syncthreads();
    }
}

__device__ __forceinline__ void acc_to_smem(
    float acc[4][4][4], char* smem, const float* __restrict__ bias, int n0)
{
    float* Cs = (float*)smem;
    const int wid = threadIdx.x >> 5;
    const int lane = threadIdx.x & 31;
    const int wm = wid >> 2, wn = wid & 3;
    const int r0 = wm * 64 + (lane >> 2);
    const int c0 = wn * 32 + 2 * (lane & 3);
    #pragma unroll
    for (int mi = 0; mi < 4; mi++) {
        #pragma unroll
        for (int nj = 0; nj < 4; nj++) {
            int r = r0 + mi * 16;
            int c = c0 + nj * 8;
            float b0 = __ldg(&bias[n0 + c]);
            float b1 = __ldg(&bias[n0 + c + 1]);
            Cs[r * CS_LD + c]           = acc[mi][nj][0] + b0;
            Cs[r * CS_LD + c + 1]       = acc[mi][nj][1] + b1;
            Cs[(r + 8) * CS_LD + c]     = acc[mi][nj][2] + b0;
            Cs[(r + 8) * CS_LD + c + 1] = acc[mi][nj][3] + b1;
        }
    }
}

// ---------------- QKV GEMM + bias + RoPE + hi/lo split epilogue ------------
__global__ __launch_bounds__(256) void qkv_mma_kernel(
    const float* __restrict__ bq, const float* __restrict__ bk,
    const float* __restrict__ bv)
{
    extern __shared__ __align__(16) char smem[];
    const int z = blockIdx.z;
    const __nv_bfloat16* Whi = g_whi + (size_t)z * C_ * C_;
    const __nv_bfloat16* Wlo = g_wlo + (size_t)z * C_ * C_;
    const float* bias = (z == 0) ? bq : (z == 1) ? bk : bv;

    const int m0 = blockIdx.x * 128;
    const int n0 = blockIdx.y * 128;

    float acc[4][4][4];
    gemm_mma(g_xhi, g_xlo, Whi, Wlo, m0, n0, smem, acc);
    acc_to_smem(acc, smem, bias, n0);
    __syncthreads();

    const float* Cs = (const float*)smem;
    const int tid = threadIdx.x;
    const int b = m0 / T_;
    const int tbase = m0 % T_;

    if (z < 2) {
        __nv_bfloat16* dHi = (z == 0) ? g_qhi : g_khi;
        __nv_bfloat16* dLo = (z == 0) ? g_qlo : g_klo;
        #pragma unroll
        for (int it = 0; it < 32; it++) {
            int p = tid + it * 256;
            int row = p >> 6;
            int q6 = p & 63;
            int hd = q6 >> 5;
            int i = q6 & 31;
            int t = tbase + row;
            int h = (n0 >> 6) + hd;
            float xr = Cs[row * CS_LD + hd * 64 + i];
            float xi = Cs[row * CS_LD + hd * 64 + i + 32];
            float cs = g_cos[t * HALF_ + i];
            float sn = g_sin[t * HALF_ + i];
            float a = xr * cs - xi * sn;
            float c = xr * sn + xi * cs;
            size_t base = ((size_t)(b * H_ + h) * T_ + t) * D_;
            __nv_bfloat16 ah = __float2bfloat16(a);
            __nv_bfloat16 ch = __float2bfloat16(c);
            dHi[base + i]      = ah;
            dHi[base + i + 32] = ch;
            dLo[base + i]      = __float2bfloat16(a - __bfloat162float(ah));
            dLo[base + i + 32] = __float2bfloat16(c - __bfloat162float(ch));
        }
    } else {
        #pragma unroll
        for (int it = 0; it < 16; it++) {
            int e = tid + it * 256;
            int row = e >> 5;
            int col = (e & 31) * 4;
            int hd = col >> 6;
            int d = col & 63;
            int t = tbase + row;
            int h = (n0 >> 6) + hd;
            float4 v4 = *(const float4*)&Cs[row * CS_LD + col];
            uint32_t h0, l0, h1, l1;
            split2(v4.x, v4.y, h0, l0);
            split2(v4.z, v4.w, h1, l1);
            size_t base = ((size_t)(b * H_ + h) * T_ + t) * D_ + d;
            ((uint32_t*)(g_vhi + base))[0] = h0;
            ((uint32_t*)(g_vhi + base))[1] = h1;
            ((uint32_t*)(g_vlo + base))[0] = l0;
            ((uint32_t*)(g_vlo + base))[1] = l1;
        }
    }
}

// ---------------- output projection GEMM -----------------------------------
__global__ __launch_bounds__(256) void proj_mma_kernel(
    const float* __restrict__ bp, float* __restrict__ out)
{
    extern __shared__ __align__(16) char smem[];
    const int m0 = blockIdx.x * 128;
    const int n0 = blockIdx.y * 128;
    const __nv_bfloat16* Whi = g_whi + (size_t)3 * C_ * C_;
    const __nv_bfloat16* Wlo = g_wlo + (size_t)3 * C_ * C_;

    float acc[4][4][4];
    gemm_mma(g_yhi, g_ylo, Whi, Wlo, m0, n0, smem, acc);
    acc_to_smem(acc, smem, bp, n0);
    __syncthreads();

    const float* Cs = (const float*)smem;
    const int tid = threadIdx.x;
    #pragma unroll
    for (int it = 0; it < 16; it++) {
        int e = tid + it * 256;
        int row = e >> 5;
        int col = (e & 31) * 4;
        float4 v4 = *(const float4*)&Cs[row * CS_LD + col];
        *(float4*)&out[(size_t)(m0 + row) * C_ + n0 + col] = v4;
    }
}

// ---------------- mma.sync causal flash attention ---------------------------
// grid (T/128, H, B), 256 threads (8 warps, 16 q-rows each), key tiles of 64.
#define SA_QHI 0
#define SA_QLO 16384
#define SA_KHI 0
#define SA_KLO 8192
#define SA_VHI 16384
#define SA_VLO 24576
#define ATT_SMEM 32768

__global__ __launch_bounds__(256) void attn_mma_kernel() {
    extern __shared__ __align__(16) char smem[];
    const uint32_t sbase = smem_u32(smem);
    const int tid = threadIdx.x;
    const int w = tid >> 5;
    const int lane = tid & 31;
    const int bx = blockIdx.x;
    const int h = blockIdx.y;
    const int b = blockIdx.z;

    const size_t head = (size_t)(b * H_ + h) * T_ * D_;
    const __nv_bfloat16* Qhi = g_qhi + head;
    const __nv_bfloat16* Qlo = g_qlo + head;
    const __nv_bfloat16* Khi = g_khi + head;
    const __nv_bfloat16* Klo = g_klo + head;
    const __nv_bfloat16* Vhi = g_vhi + head;
    const __nv_bfloat16* Vlo = g_vlo + head;

    // ---- stage Q (128 x 64 bf16 hi/lo), load per-warp A fragments ----
    #pragma unroll
    for (int it = 0; it < 4; it++) {
        int idx = tid + it * 256;            // 0..1023 16B chunks
        int r = idx >> 3;
        int cb = idx & 7;
        uint32_t off = (uint32_t)(r * 128 + cb * 16);
        uint32_t sw = off ^ (uint32_t)((r & 7) << 4);
        size_t g = (size_t)(bx * 128 + r) * D_ + cb * 8;
        *(uint4*)(smem + SA_QHI + sw) = *(const uint4*)(Qhi + g);
        *(uint4*)(smem + SA_QLO + sw) = *(const uint4*)(Qlo + g);
    }
    __syncthreads();

    uint32_t qh[4][4], ql[4][4];
    {
        const int a_row = lane & 15;
        const int a_kh = lane >> 4;
        #pragma unroll
        for (int kt = 0; kt < 4; kt++) {
            int R = w * 16 + a_row;
            int cb = kt * 2 + a_kh;
            uint32_t off = (uint32_t)(R * 128 + cb * 16);
            uint32_t sw = off ^ (uint32_t)((R & 7) << 4);
            ldsm_x4(sbase + SA_QHI + sw, qh[kt]);
            ldsm_x4(sbase + SA_QLO + sw, ql[kt]);
        }
    }
    __syncthreads();

    // softmax state
    const int q0 = bx * 128 + w * 16 + (lane >> 2);
    const int q1 = q0 + 8;
    float m0 = -INFINITY, m1 = -INFINITY, l0 = 0.f, l1 = 0.f;
    float acc_o[8][4];
    #pragma unroll
    for (int j = 0; j < 8; j++)
        #pragma unroll
        for (int e = 0; e < 4; e++) acc_o[j][e] = 0.f;

    const float S2 = 0.125f * 1.44269504088896f;   // scale * log2(e)

    const int bg = lane >> 3;
    const int b_row = ((bg >> 1) << 3) + (lane & 7);
    const int b_kh = bg & 1;
    const int l7 = lane & 7;
    const int ntiles = 2 * bx + 2;

    for (int ti = 0; ti < ntiles; ti++) {
        // ---- stage K,V hi/lo tiles (64 x 64 bf16 each) ----
        #pragma unroll
        for (int it = 0; it < 8; it++) {
            int idx = tid + it * 256;         // 0..2047
            int sel = idx >> 9;               // 0..3
            int sub = idx & 511;
            int r = sub >> 3;
            int cb = sub & 7;
            uint32_t off = (uint32_t)(r * 128 + cb * 16);
            uint32_t sw = off ^ (uint32_t)((r & 7) << 4);
            size_t g = (size_t)(ti * 64 + r) * D_ + cb * 8;
            const __nv_bfloat16* src = (sel == 0) ? Khi : (sel == 1) ? Klo
                                      : (sel == 2) ? Vhi : Vlo;
            int dstoff = (sel == 0) ? SA_KHI : (sel == 1) ? SA_KLO
                       : (sel == 2) ? SA_VHI : SA_VLO;
            *(uint4*)(smem + dstoff + sw) = *(const uint4*)(src + g);
        }
        __syncthreads();

        // ---- S = Q K^T (hi/lo split, 3 mmas) ----
        float acc[8][4];
        #pragma unroll
        for (int j = 0; j < 8; j++)
            #pragma unroll
            for (int e = 0; e < 4; e++) acc[j][e] = 0.f;

        #pragma unroll
        for (int kt = 0; kt < 4; kt++) {
            uint32_t bh[8][2], bl[8][2];
            #pragma unroll
            for (int np = 0; np < 4; np++) {
                int R = np * 16 + b_row;
                int cb = kt * 2 + b_kh;
                uint32_t off = (uint32_t)(R * 128 + cb * 16);
                uint32_t sw = off ^ (uint32_t)((R & 7) << 4);
                ldsm_x4(sbase + SA_KHI + sw, &bh[np * 2][0]);
                ldsm_x4(sbase + SA_KLO + sw, &bl[np * 2][0]);
            }
            #pragma unroll
            for (int j = 0; j < 8; j++) {
                mma16816(acc[j], qh[kt], bh[j]);
                mma16816(acc[j], qh[kt], bl[j]);
                mma16816(acc[j], ql[kt], bh[j]);
            }
        }

        // ---- causal mask (only the last two tiles can cross the diagonal) ----
        if (ti >= 2 * bx) {
            #pragma unroll
            for (int j = 0; j < 8; j++) {
                int s0 = ti * 64 + 8 * j + 2 * (lane & 3);
                if (s0     > q0) acc[j][0] = -INFINITY;
                if (s0 + 1 > q0) acc[j][1] = -INFINITY;
                if (s0     > q1) acc[j][2] = -INFINITY;
                if (s0 + 1 > q1) acc[j][3] = -INFINITY;
            }
        }

        // ---- online softmax ----
        float mt0 = -INFINITY, mt1 = -INFINITY;
        #pragma unroll
        for (int j = 0; j < 8; j++) {
            mt0 = fmaxf(mt0, fmaxf(acc[j][0], acc[j][1]));
            mt1 = fmaxf(mt1, fmaxf(acc[j][2], acc[j][3]));
        }
        mt0 = fmaxf(mt0, __shfl_xor_sync(0xffffffff, mt0, 1));
        mt0 = fmaxf(mt0, __shfl_xor_sync(0xffffffff, mt0, 2));
        mt1 = fmaxf(mt1, __shfl_xor_sync(0xffffffff, mt1, 1));
        mt1 = fmaxf(mt1, __shfl_xor_sync(0xffffffff, mt1, 2));

        float mn0 = fmaxf(m0, mt0);
        float mn1 = fmaxf(m1, mt1);
        float c0 = exp2f((m0 - mn0) * S2);
        float c1 = exp2f((m1 - mn1) * S2);
        l0 *= c0; l1 *= c1;
        #pragma unroll
        for (int j = 0; j < 8; j++) {
            acc_o[j][0] *= c0; acc_o[j][1] *= c0;
            acc_o[j][2] *= c1; acc_o[j][3] *= c1;
        }
        float fm0 = mn0 * S2, fm1 = mn1 * S2;
        #pragma unroll
        for (int j = 0; j < 8; j++) {
            float p0 = exp2f(acc[j][0] * S2 - fm0);
            float p1 = exp2f(acc[j][1] * S2 - fm0);
            float p2 = exp2f(acc[j][2] * S2 - fm1);
            float p3 = exp2f(acc[j][3] * S2 - fm1);
            l0 += p0 + p1;
            l1 += p2 + p3;
            acc[j][0] = p0; acc[j][1] = p1; acc[j][2] = p2; acc[j][3] = p3;
        }
        m0 = mn0; m1 = mn1;

        // ---- O += P V (P hi/lo on the fly, V hi/lo, 3 mmas) ----
        #pragma unroll
        for (int kt = 0; kt < 4; kt++) {
            uint32_t ph[4], pl[4];
            split2(acc[2 * kt][0],     acc[2 * kt][1],     ph[0], pl[0]);
            split2(acc[2 * kt][2],     acc[2 * kt][3],     ph[1], pl[1]);
            split2(acc[2 * kt + 1][0], acc[2 * kt + 1][1], ph[2], pl[2]);
            split2(acc[2 * kt + 1][2], acc[2 * kt + 1][3], ph[3], pl[3]);
            #pragma unroll
            for (int np = 0; np < 4; np++) {
                // trans-ldmatrix: block bg covers V rows kt*16+(bg&1)*8+l7,
                // cols np*16+(bg>>1)*8
                int srow = kt * 16 + ((bg & 1) << 3) + l7;
                int dcol = np * 16 + ((bg >> 1) << 3);
                uint32_t off = (uint32_t)(srow * 128 + dcol * 2);
                uint32_t sw = off ^ (uint32_t)((srow & 7) << 4);
                uint32_t vh[4], vl[4];
                ldsm_x4_trans(sbase + SA_VHI + sw, vh);
                ldsm_x4_trans(sbase + SA_VLO + sw, vl);
                mma16816(acc_o[2 * np],     ph, &vh[0]);
                mma16816(acc_o[2 * np],     ph, &vl[0]);
                mma16816(acc_o[2 * np],     pl, &vh[0]);
                mma16816(acc_o[2 * np + 1], ph, &vh[2]);
                mma16816(acc_o[2 * np + 1], ph, &vl[2]);
                mma16816(acc_o[2 * np + 1], pl, &vh[2]);
            }
        }
        __syncthreads();
    }

    // ---- finalize: reduce l over the lane quad, normalize, emit y hi/lo ----
    l0 += __shfl_xor_sync(0xffffffff, l0, 1);
    l0 += __shfl_xor_sync(0xffffffff, l0, 2);
    l1 += __shfl_xor_sync(0xffffffff, l1, 1);
    l1 += __shfl_xor_sync(0xffffffff, l1, 2);
    float inv0 = 1.f / l0;
    float inv1 = 1.f / l1;

    const size_t row0 = (size_t)(b * T_ + q0) * C_ + h * 64;
    const size_t row1 = (size_t)(b * T_ + q1) * C_ + h * 64;
    #pragma unroll
    for (int j = 0; j < 8; j++) {
        int d = 8 * j + 2 * (lane & 3);
        uint32_t hi, lo;
        split2(acc_o[j][0] * inv0, acc_o[j][1] * inv0, hi, lo);
        *(uint32_t*)(g_yhi + row0 + d) = hi;
        *(uint32_t*)(g_ylo + row0 + d) = lo;
        split2(acc_o[j][2] * inv1, acc_o[j][3] * inv1, hi, lo);
        *(uint32_t*)(g_yhi + row1 + d) = hi;
        *(uint32_t*)(g_ylo + row1 + d) = lo;
    }
}

// ---------------- launch ---------------------------------------------------
extern "C" void kernel_launch(void* const* d_in, const int* in_sizes, int n_in,
                              void* d_out, int out_size)
{
    const float* x  = (const float*)d_in[0];
    const float* wq = (const float*)d_in[1];
    const float* bq = (const float*)d_in[2];
    const float* wk = (const float*)d_in[3];
    const float* bk = (const float*)d_in[4];
    const float* wv = (const float*)d_in[5];
    const float* bv = (const float*)d_in[6];
    const float* wp = (const float*)d_in[7];
    const float* bp = (const float*)d_in[8];
    float* out = (float*)d_out;

    static bool attr_done = false;
    if (!attr_done) {
        cudaFuncSetAttribute(qkv_mma_kernel,
                             cudaFuncAttributeMaxDynamicSharedMemorySize, SMEM_BYTES);
        cudaFuncSetAttribute(proj_mma_kernel,
                             cudaFuncAttributeMaxDynamicSharedMemorySize, SMEM_BYTES);
        cudaFuncSetAttribute(attn_mma_kernel,
                             cudaFuncAttributeMaxDynamicSharedMemorySize, ATT_SMEM);
        attr_done = true;
    }

    __nv_bfloat16 *p_xhi, *p_xlo, *p_whi, *p_wlo;
    cudaGetSymbolAddress((void**)&p_xhi, g_xhi);
    cudaGetSymbolAddress((void**)&p_xlo, g_xlo);
    cudaGetSymbolAddress((void**)&p_whi, g_whi);
    cudaGetSymbolAddress((void**)&p_wlo, g_wlo);

    rope_init_kernel<<<(T_ * HALF_ + 255) / 256, 256>>>();

    split_kernel<<<(M_ * C_ / 4 + 255) / 256, 256>>>(x, p_xhi, p_xlo, M_ * C_ / 4);
    split_kernel<<<(C_ * C_ / 4 + 255) / 256, 256>>>(wq, p_whi + 0 * (size_t)C_ * C_,
                                                     p_wlo + 0 * (size_t)C_ * C_, C_ * C_ / 4);
    split_kernel<<<(C_ * C_ / 4 + 255) / 256, 256>>>(wk, p_whi + 1 * (size_t)C_ * C_,
                                                     p_wlo + 1 * (size_t)C_ * C_, C_ * C_ / 4);
    split_kernel<<<(C_ * C_ / 4 + 255) / 256, 256>>>(wv, p_whi + 2 * (size_t)C_ * C_,
                                                     p_wlo + 2 * (size_t)C_ * C_, C_ * C_ / 4);
    split_kernel<<<(C_ * C_ / 4 + 255) / 256, 256>>>(wp, p_whi + 3 * (size_t)C_ * C_,
                                                     p_wlo + 3 * (size_t)C_ * C_, C_ * C_ / 4);

    qkv_mma_kernel<<<dim3(M_ / 128, C_ / 128, 3), 256, SMEM_BYTES>>>(bq, bk, bv);
    attn_mma_kernel<<<dim3(T_ / 128, H_, B_), 256, ATT_SMEM>>>();
    proj_mma_kernel<<<dim3(M_ / 128, C_ / 128), 256, SMEM_BYTES>>>(bp, out);
}

// round 6
// speedup vs baseline: 4.0991x; 1.1442x over previous
#include <cuda_runtime.h>
#include <cuda_bf16.h>
#include <math.h>
#include <stdint.h>

#define B_ 4
#define T_ 2048
#define C_ 1024
#define H_ 16
#define D_ 64
#define M_ (B_ * T_)          // 8192 rows
#define HALF_ 32              // D/2 for RoPE
#define NCHUNK_ (C_ / 64)     // 16 K-chunks of 64 bf16

// ---------------- scratch (device globals: no runtime allocation) ----------
__device__ float g_cos[T_ * HALF_];
__device__ float g_sin[T_ * HALF_];
__device__ __nv_bfloat16 g_xhi[(size_t)M_ * C_];
__device__ __nv_bfloat16 g_xlo[(size_t)M_ * C_];
__device__ __nv_bfloat16 g_whi[(size_t)4 * C_ * C_];   // wq,wk,wv,wp
__device__ __nv_bfloat16 g_wlo[(size_t)4 * C_ * C_];
__device__ __nv_bfloat16 g_yhi[(size_t)M_ * C_];
__device__ __nv_bfloat16 g_ylo[(size_t)M_ * C_];
__device__ __nv_bfloat16 g_qhi[(size_t)B_ * H_ * T_ * D_];
__device__ __nv_bfloat16 g_qlo[(size_t)B_ * H_ * T_ * D_];
__device__ __nv_bfloat16 g_khi[(size_t)B_ * H_ * T_ * D_];
__device__ __nv_bfloat16 g_klo[(size_t)B_ * H_ * T_ * D_];
__device__ __nv_bfloat16 g_vhi[(size_t)B_ * H_ * T_ * D_];
__device__ __nv_bfloat16 g_vlo[(size_t)B_ * H_ * T_ * D_];

// ---------------- PTX helpers (portable: sm_80+ features only) -------------
__device__ __forceinline__ uint32_t smem_u32(const void* p) {
    uint32_t a;
    asm("{ .reg .u64 t; cvta.to.shared.u64 t, %1; cvt.u32.u64 %0, t; }"
        : "=r"(a) : "l"(p));
    return a;
}

__device__ __forceinline__ void cp16(uint32_t saddr, const void* g) {
    asm volatile("cp.async.cg.shared.global [%0], [%1], 16;" :: "r"(saddr), "l"(g));
}
__device__ __forceinline__ void cp_commit() {
    asm volatile("cp.async.commit_group;" ::: "memory");
}
template <int N> __device__ __forceinline__ void cp_wait() {
    asm volatile("cp.async.wait_group %0;" :: "n"(N) : "memory");
}

__device__ __forceinline__ void ldsm_x4(uint32_t addr, uint32_t* r) {
    asm volatile("ldmatrix.sync.aligned.m8n8.x4.shared.b16 {%0,%1,%2,%3}, [%4];"
        : "=r"(r[0]), "=r"(r[1]), "=r"(r[2]), "=r"(r[3]) : "r"(addr));
}

__device__ __forceinline__ void ldsm_x4_trans(uint32_t addr, uint32_t* r) {
    asm volatile("ldmatrix.sync.aligned.m8n8.x4.trans.shared.b16 {%0,%1,%2,%3}, [%4];"
        : "=r"(r[0]), "=r"(r[1]), "=r"(r[2]), "=r"(r[3]) : "r"(addr));
}

__device__ __forceinline__ void mma16816(float* d, const uint32_t* a, const uint32_t* b) {
    asm volatile(
        "mma.sync.aligned.m16n8k16.row.col.f32.bf16.bf16.f32 "
        "{%0,%1,%2,%3}, {%4,%5,%6,%7}, {%8,%9}, {%0,%1,%2,%3};"
        : "+f"(d[0]), "+f"(d[1]), "+f"(d[2]), "+f"(d[3])
        : "r"(a[0]), "r"(a[1]), "r"(a[2]), "r"(a[3]), "r"(b[0]), "r"(b[1]));
}

__device__ __forceinline__ void split2(float a, float b, uint32_t& hi, uint32_t& lo) {
    __nv_bfloat16 h0 = __float2bfloat16(a);
    __nv_bfloat16 h1 = __float2bfloat16(b);
    __nv_bfloat16 l0 = __float2bfloat16(a - __bfloat162float(h0));
    __nv_bfloat16 l1 = __float2bfloat16(b - __bfloat162float(h1));
    __nv_bfloat162 H = __halves2bfloat162(h0, h1);
    __nv_bfloat162 L = __halves2bfloat162(l0, l1);
    hi = *(uint32_t*)&H;
    lo = *(uint32_t*)&L;
}

// ---------------- smem layout (GEMM): two 64KB stages -----------------------
// stage s at s*65536: A_HI +0, A_LO +16384, B_HI +32768, B_LO +49152
#define STG_ 65536
#define CS_LD 132
#define SMEM_BYTES (2 * STG_)           // 131072 (epilogue Cs 67584 fits)

// ---------------- RoPE table -----------------------------------------------
__global__ void rope_init_kernel() {
    int idx = blockIdx.x * blockDim.x + threadIdx.x;
    if (idx >= T_ * HALF_) return;
    int t = idx / HALF_;
    int i = idx % HALF_;
    double alpha = pow(10000.0, -(double)i / (double)HALF_);
    double ang = (double)t * alpha;
    g_cos[idx] = (float)cos(ang);
    g_sin[idx] = (float)sin(ang);
}

// ---------------- fused fp32 -> bf16 hi/lo split (x + 4 weights) -----------
__global__ __launch_bounds__(256) void split_all_kernel(
    const float* __restrict__ x, const float* __restrict__ wq,
    const float* __restrict__ wk, const float* __restrict__ wv,
    const float* __restrict__ wp)
{
    const int NX = M_ * C_ / 4;          // 2M float4
    const int NW = C_ * C_ / 4;          // 256K float4
    int i = blockIdx.x * blockDim.x + threadIdx.x;
    if (i >= NX + 4 * NW) return;

    const float* src;
    __nv_bfloat16 *hi, *lo;
    int off;
    if (i < NX) {
        src = x; hi = g_xhi; lo = g_xlo; off = i;
    } else {
        int j = i - NX;
        int w = j >> 18;                 // j / NW  (NW = 2^18)
        off = j & (NW - 1);
        src = (w == 0) ? wq : (w == 1) ? wk : (w == 2) ? wv : wp;
        hi = g_whi + (size_t)w * C_ * C_;
        lo = g_wlo + (size_t)w * C_ * C_;
    }
    float4 v = ((const float4*)src)[off];
    uint32_t h0, l0, h1, l1;
    split2(v.x, v.y, h0, l0);
    split2(v.z, v.w, h1, l1);
    ((uint32_t*)hi)[2 * off + 0] = h0;
    ((uint32_t*)hi)[2 * off + 1] = h1;
    ((uint32_t*)lo)[2 * off + 0] = l0;
    ((uint32_t*)lo)[2 * off + 1] = l1;
}

// ---------------- pipelined mma.sync GEMM mainloop -------------------------
__device__ __forceinline__ void gemm_issue_chunk(
    const __nv_bfloat16* __restrict__ Ahi, const __nv_bfloat16* __restrict__ Alo,
    const __nv_bfloat16* __restrict__ Bhi, const __nv_bfloat16* __restrict__ Blo,
    int m0, int n0, int kc, uint32_t sb)
{
    const int tid = threadIdx.x;
    const int k0 = kc * 64;
    #pragma unroll
    for (int it = 0; it < 4; it++) {
        int idx = tid + it * 256;
        int r = idx >> 3;
        int cb = idx & 7;
        uint32_t off = (uint32_t)(r * 128 + cb * 16);
        uint32_t sw = off ^ (uint32_t)((r & 7) << 4);
        const size_t ga = (size_t)(m0 + r) * C_ + k0 + cb * 8;
        const size_t gb = (size_t)(n0 + r) * C_ + k0 + cb * 8;
        cp16(sb + sw,         Ahi + ga);
        cp16(sb + 16384 + sw, Alo + ga);
        cp16(sb + 32768 + sw, Bhi + gb);
        cp16(sb + 49152 + sw, Blo + gb);
    }
    cp_commit();
}

__device__ __forceinline__ void gemm_mma(
    const __nv_bfloat16* __restrict__ Ahi, const __nv_bfloat16* __restrict__ Alo,
    const __nv_bfloat16* __restrict__ Bhi, const __nv_bfloat16* __restrict__ Blo,
    int m0, int n0, char* smem, float acc[4][4][4])
{
    const int tid = threadIdx.x;
    const int wid = tid >> 5;
    const int lane = tid & 31;
    const int wm = wid >> 2;
    const int wn = wid & 3;
    const uint32_t sbase = smem_u32(smem);

    #pragma unroll
    for (int mi = 0; mi < 4; mi++)
        #pragma unroll
        for (int nj = 0; nj < 4; nj++)
            #pragma unroll
            for (int e = 0; e < 4; e++) acc[mi][nj][e] = 0.f;

    const int a_row = lane & 15;
    const int a_kh  = lane >> 4;
    const int bg    = lane >> 3;
    const int b_row = ((bg >> 1) << 3) + (lane & 7);
    const int b_kh  = bg & 1;

    gemm_issue_chunk(Ahi, Alo, Bhi, Blo, m0, n0, 0, sbase);

    for (int kc = 0; kc < NCHUNK_; kc++) {
        if (kc + 1 < NCHUNK_) {
            gemm_issue_chunk(Ahi, Alo, Bhi, Blo, m0, n0, kc + 1,
                             sbase + ((kc + 1) & 1) * STG_);
            cp_wait<1>();
        } else {
            cp_wait<0>();
        }
        __syncthreads();

        const uint32_t st = sbase + (kc & 1) * STG_;
        #pragma unroll
        for (int kk = 0; kk < 4; kk++) {
            uint32_t bh[4][2], bl[4][2];
            #pragma unroll
            for (int np = 0; np < 2; np++) {
                int R = wn * 32 + np * 16 + b_row;
                int cb = kk * 2 + b_kh;
                uint32_t off = (uint32_t)(R * 128 + cb * 16);
                uint32_t sw = off ^ (uint32_t)((R & 7) << 4);
                ldsm_x4(st + 32768 + sw, &bh[np * 2][0]);
                ldsm_x4(st + 49152 + sw, &bl[np * 2][0]);
            }
            #pragma unroll
            for (int mi = 0; mi < 4; mi++) {
                uint32_t ah[4], al[4];
                int R = wm * 64 + mi * 16 + a_row;
                int cb = kk * 2 + a_kh;
                uint32_t off = (uint32_t)(R * 128 + cb * 16);
                uint32_t sw = off ^ (uint32_t)((R & 7) << 4);
                ldsm_x4(st + sw, ah);
                ldsm_x4(st + 16384 + sw, al);
                #pragma unroll
                for (int nj = 0; nj < 4; nj++) {
                    mma16816(acc[mi][nj], ah, bh[nj]);
                    mma16816(acc[mi][nj], ah, bl[nj]);
                    mma16816(acc[mi][nj], al, bh[nj]);
                }
            }
        }
        __syncthreads();
    }
}

__device__ __forceinline__ void acc_to_smem(
    float acc[4][4][4], char* smem, const float* __restrict__ bias, int n0)
{
    float* Cs = (float*)smem;
    const int wid = threadIdx.x >> 5;
    const int lane = threadIdx.x & 31;
    const int wm = wid >> 2, wn = wid & 3;
    const int r0 = wm * 64 + (lane >> 2);
    const int c0 = wn * 32 + 2 * (lane & 3);
    #pragma unroll
    for (int mi = 0; mi < 4; mi++) {
        #pragma unroll
        for (int nj = 0; nj < 4; nj++) {
            int r = r0 + mi * 16;
            int c = c0 + nj * 8;
            float b0 = __ldg(&bias[n0 + c]);
            float b1 = __ldg(&bias[n0 + c + 1]);
            Cs[r * CS_LD + c]           = acc[mi][nj][0] + b0;
            Cs[r * CS_LD + c + 1]       = acc[mi][nj][1] + b1;
            Cs[(r + 8) * CS_LD + c]     = acc[mi][nj][2] + b0;
            Cs[(r + 8) * CS_LD + c + 1] = acc[mi][nj][3] + b1;
        }
    }
}

// ---------------- QKV GEMM + bias + RoPE + hi/lo split epilogue ------------
__global__ __launch_bounds__(256) void qkv_mma_kernel(
    const float* __restrict__ bq, const float* __restrict__ bk,
    const float* __restrict__ bv)
{
    extern __shared__ __align__(16) char smem[];
    const int z = blockIdx.z;
    const __nv_bfloat16* Whi = g_whi + (size_t)z * C_ * C_;
    const __nv_bfloat16* Wlo = g_wlo + (size_t)z * C_ * C_;
    const float* bias = (z == 0) ? bq : (z == 1) ? bk : bv;

    const int m0 = blockIdx.x * 128;
    const int n0 = blockIdx.y * 128;

    float acc[4][4][4];
    gemm_mma(g_xhi, g_xlo, Whi, Wlo, m0, n0, smem, acc);
    acc_to_smem(acc, smem, bias, n0);
    __syncthreads();

    const float* Cs = (const float*)smem;
    const int tid = threadIdx.x;
    const int b = m0 / T_;
    const int tbase = m0 % T_;

    if (z < 2) {
        __nv_bfloat16* dHi = (z == 0) ? g_qhi : g_khi;
        __nv_bfloat16* dLo = (z == 0) ? g_qlo : g_klo;
        #pragma unroll
        for (int it = 0; it < 32; it++) {
            int p = tid + it * 256;
            int row = p >> 6;
            int q6 = p & 63;
            int hd = q6 >> 5;
            int i = q6 & 31;
            int t = tbase + row;
            int h = (n0 >> 6) + hd;
            float xr = Cs[row * CS_LD + hd * 64 + i];
            float xi = Cs[row * CS_LD + hd * 64 + i + 32];
            float cs = g_cos[t * HALF_ + i];
            float sn = g_sin[t * HALF_ + i];
            float a = xr * cs - xi * sn;
            float c = xr * sn + xi * cs;
            size_t base = ((size_t)(b * H_ + h) * T_ + t) * D_;
            __nv_bfloat16 ah = __float2bfloat16(a);
            __nv_bfloat16 ch = __float2bfloat16(c);
            dHi[base + i]      = ah;
            dHi[base + i + 32] = ch;
            dLo[base + i]      = __float2bfloat16(a - __bfloat162float(ah));
            dLo[base + i + 32] = __float2bfloat16(c - __bfloat162float(ch));
        }
    } else {
        #pragma unroll
        for (int it = 0; it < 16; it++) {
            int e = tid + it * 256;
            int row = e >> 5;
            int col = (e & 31) * 4;
            int hd = col >> 6;
            int d = col & 63;
            int t = tbase + row;
            int h = (n0 >> 6) + hd;
            float4 v4 = *(const float4*)&Cs[row * CS_LD + col];
            uint32_t h0, l0, h1, l1;
            split2(v4.x, v4.y, h0, l0);
            split2(v4.z, v4.w, h1, l1);
            size_t base = ((size_t)(b * H_ + h) * T_ + t) * D_ + d;
            ((uint32_t*)(g_vhi + base))[0] = h0;
            ((uint32_t*)(g_vhi + base))[1] = h1;
            ((uint32_t*)(g_vlo + base))[0] = l0;
            ((uint32_t*)(g_vlo + base))[1] = l1;
        }
    }
}

// ---------------- output projection GEMM -----------------------------------
__global__ __launch_bounds__(256) void proj_mma_kernel(
    const float* __restrict__ bp, float* __restrict__ out)
{
    extern __shared__ __align__(16) char smem[];
    const int m0 = blockIdx.x * 128;
    const int n0 = blockIdx.y * 128;
    const __nv_bfloat16* Whi = g_whi + (size_t)3 * C_ * C_;
    const __nv_bfloat16* Wlo = g_wlo + (size_t)3 * C_ * C_;

    float acc[4][4][4];
    gemm_mma(g_yhi, g_ylo, Whi, Wlo, m0, n0, smem, acc);
    acc_to_smem(acc, smem, bp, n0);
    __syncthreads();

    const float* Cs = (const float*)smem;
    const int tid = threadIdx.x;
    #pragma unroll
    for (int it = 0; it < 16; it++) {
        int e = tid + it * 256;
        int row = e >> 5;
        int col = (e & 31) * 4;
        float4 v4 = *(const float4*)&Cs[row * CS_LD + col];
        *(float4*)&out[(size_t)(m0 + row) * C_ + n0 + col] = v4;
    }
}

// ---------------- mma.sync causal flash attention (pipelined K/V) ----------
// grid (T/128, H, B), 256 threads; K/V tiles of 64 in two 32KB stages.
// stage s at s*32768: K_HI +0, K_LO +8192, V_HI +16384, V_LO +24576
#define ASTG_ 32768
#define ATT_SMEM (2 * ASTG_)

__device__ __forceinline__ void attn_issue_tile(
    const __nv_bfloat16* __restrict__ Khi, const __nv_bfloat16* __restrict__ Klo,
    const __nv_bfloat16* __restrict__ Vhi, const __nv_bfloat16* __restrict__ Vlo,
    int ti, uint32_t sb)
{
    const int tid = threadIdx.x;
    #pragma unroll
    for (int it = 0; it < 8; it++) {
        int idx = tid + it * 256;         // 0..2047
        int sel = idx >> 9;               // 0..3
        int sub = idx & 511;
        int r = sub >> 3;
        int cb = sub & 7;
        uint32_t off = (uint32_t)(r * 128 + cb * 16);
        uint32_t sw = off ^ (uint32_t)((r & 7) << 4);
        size_t g = (size_t)(ti * 64 + r) * D_ + cb * 8;
        const __nv_bfloat16* src = (sel == 0) ? Khi : (sel == 1) ? Klo
                                  : (sel == 2) ? Vhi : Vlo;
        cp16(sb + sel * 8192 + sw, src + g);
    }
    cp_commit();
}

__global__ __launch_bounds__(256) void attn_mma_kernel() {
    extern __shared__ __align__(16) char smem[];
    const uint32_t sbase = smem_u32(smem);
    const int tid = threadIdx.x;
    const int w = tid >> 5;
    const int lane = tid & 31;
    const int bx = blockIdx.x;
    const int h = blockIdx.y;
    const int b = blockIdx.z;

    const size_t head = (size_t)(b * H_ + h) * T_ * D_;
    const __nv_bfloat16* Qhi = g_qhi + head;
    const __nv_bfloat16* Qlo = g_qlo + head;
    const __nv_bfloat16* Khi = g_khi + head;
    const __nv_bfloat16* Klo = g_klo + head;
    const __nv_bfloat16* Vhi = g_vhi + head;
    const __nv_bfloat16* Vlo = g_vlo + head;

    // ---- stage Q into stage0 region, load per-warp A fragments ----
    #pragma unroll
    for (int it = 0; it < 4; it++) {
        int idx = tid + it * 256;
        int r = idx >> 3;
        int cb = idx & 7;
        uint32_t off = (uint32_t)(r * 128 + cb * 16);
        uint32_t sw = off ^ (uint32_t)((r & 7) << 4);
        size_t g = (size_t)(bx * 128 + r) * D_ + cb * 8;
        *(uint4*)(smem + sw)         = *(const uint4*)(Qhi + g);
        *(uint4*)(smem + 16384 + sw) = *(const uint4*)(Qlo + g);
    }
    __syncthreads();

    uint32_t qh[4][4], ql[4][4];
    {
        const int a_row = lane & 15;
        const int a_kh = lane >> 4;
        #pragma unroll
        for (int kt = 0; kt < 4; kt++) {
            int R = w * 16 + a_row;
            int cb = kt * 2 + a_kh;
            uint32_t off = (uint32_t)(R * 128 + cb * 16);
            uint32_t sw = off ^ (uint32_t)((R & 7) << 4);
            ldsm_x4(sbase + sw, qh[kt]);
            ldsm_x4(sbase + 16384 + sw, ql[kt]);
        }
    }
    __syncthreads();   // all warps done with Q region before tile0 overwrites it

    const int q0 = bx * 128 + w * 16 + (lane >> 2);
    const int q1 = q0 + 8;
    float m0 = -INFINITY, m1 = -INFINITY, l0 = 0.f, l1 = 0.f;
    float acc_o[8][4];
    #pragma unroll
    for (int j = 0; j < 8; j++)
        #pragma unroll
        for (int e = 0; e < 4; e++) acc_o[j][e] = 0.f;

    const float S2 = 0.125f * 1.44269504088896f;

    const int bg = lane >> 3;
    const int b_row = ((bg >> 1) << 3) + (lane & 7);
    const int b_kh = bg & 1;
    const int l7 = lane & 7;
    const int ntiles = 2 * bx + 2;

    attn_issue_tile(Khi, Klo, Vhi, Vlo, 0, sbase);

    for (int ti = 0; ti < ntiles; ti++) {
        if (ti + 1 < ntiles) {
            attn_issue_tile(Khi, Klo, Vhi, Vlo, ti + 1,
                            sbase + ((ti + 1) & 1) * ASTG_);
            cp_wait<1>();
        } else {
            cp_wait<0>();
        }
        __syncthreads();

        const uint32_t st = sbase + (ti & 1) * ASTG_;

        // ---- S = Q K^T (hi/lo split, 3 mmas) ----
        float acc[8][4];
        #pragma unroll
        for (int j = 0; j < 8; j++)
            #pragma unroll
            for (int e = 0; e < 4; e++) acc[j][e] = 0.f;

        #pragma unroll
        for (int kt = 0; kt < 4; kt++) {
            uint32_t bh[8][2], bl[8][2];
            #pragma unroll
            for (int np = 0; np < 4; np++) {
                int R = np * 16 + b_row;
                int cb = kt * 2 + b_kh;
                uint32_t off = (uint32_t)(R * 128 + cb * 16);
                uint32_t sw = off ^ (uint32_t)((R & 7) << 4);
                ldsm_x4(st + sw, &bh[np * 2][0]);
                ldsm_x4(st + 8192 + sw, &bl[np * 2][0]);
            }
            #pragma unroll
            for (int j = 0; j < 8; j++) {
                mma16816(acc[j], qh[kt], bh[j]);
                mma16816(acc[j], qh[kt], bl[j]);
                mma16816(acc[j], ql[kt], bh[j]);
            }
        }

        // ---- causal mask ----
        if (ti >= 2 * bx) {
            #pragma unroll
            for (int j = 0; j < 8; j++) {
                int s0 = ti * 64 + 8 * j + 2 * (lane & 3);
                if (s0     > q0) acc[j][0] = -INFINITY;
                if (s0 + 1 > q0) acc[j][1] = -INFINITY;
                if (s0     > q1) acc[j][2] = -INFINITY;
                if (s0 + 1 > q1) acc[j][3] = -INFINITY;
            }
        }

        // ---- online softmax ----
        float mt0 = -INFINITY, mt1 = -INFINITY;
        #pragma unroll
        for (int j = 0; j < 8; j++) {
            mt0 = fmaxf(mt0, fmaxf(acc[j][0], acc[j][1]));
            mt1 = fmaxf(mt1, fmaxf(acc[j][2], acc[j][3]));
        }
        mt0 = fmaxf(mt0, __shfl_xor_sync(0xffffffff, mt0, 1));
        mt0 = fmaxf(mt0, __shfl_xor_sync(0xffffffff, mt0, 2));
        mt1 = fmaxf(mt1, __shfl_xor_sync(0xffffffff, mt1, 1));
        mt1 = fmaxf(mt1, __shfl_xor_sync(0xffffffff, mt1, 2));

        float mn0 = fmaxf(m0, mt0);
        float mn1 = fmaxf(m1, mt1);
        float c0 = exp2f((m0 - mn0) * S2);
        float c1 = exp2f((m1 - mn1) * S2);
        l0 *= c0; l1 *= c1;
        #pragma unroll
        for (int j = 0; j < 8; j++) {
            acc_o[j][0] *= c0; acc_o[j][1] *= c0;
            acc_o[j][2] *= c1; acc_o[j][3] *= c1;
        }
        float fm0 = mn0 * S2, fm1 = mn1 * S2;
        #pragma unroll
        for (int j = 0; j < 8; j++) {
            float p0 = exp2f(acc[j][0] * S2 - fm0);
            float p1 = exp2f(acc[j][1] * S2 - fm0);
            float p2 = exp2f(acc[j][2] * S2 - fm1);
            float p3 = exp2f(acc[j][3] * S2 - fm1);
            l0 += p0 + p1;
            l1 += p2 + p3;
            acc[j][0] = p0; acc[j][1] = p1; acc[j][2] = p2; acc[j][3] = p3;
        }
        m0 = mn0; m1 = mn1;

        // ---- O += P V (P split hi/lo on the fly, 3 mmas) ----
        #pragma unroll
        for (int kt = 0; kt < 4; kt++) {
            uint32_t ph[4], pl[4];
            split2(acc[2 * kt][0],     acc[2 * kt][1],     ph[0], pl[0]);
            split2(acc[2 * kt][2],     acc[2 * kt][3],     ph[1], pl[1]);
            split2(acc[2 * kt + 1][0], acc[2 * kt + 1][1], ph[2], pl[2]);
            split2(acc[2 * kt + 1][2], acc[2 * kt + 1][3], ph[3], pl[3]);
            #pragma unroll
            for (int np = 0; np < 4; np++) {
                int srow = kt * 16 + ((bg & 1) << 3) + l7;
                int dcol = np * 16 + ((bg >> 1) << 3);
                uint32_t off = (uint32_t)(srow * 128 + dcol * 2);
                uint32_t sw = off ^ (uint32_t)((srow & 7) << 4);
                uint32_t vh[4], vl[4];
                ldsm_x4_trans(st + 16384 + sw, vh);
                ldsm_x4_trans(st + 24576 + sw, vl);
                mma16816(acc_o[2 * np],     ph, &vh[0]);
                mma16816(acc_o[2 * np],     ph, &vl[0]);
                mma16816(acc_o[2 * np],     pl, &vh[0]);
                mma16816(acc_o[2 * np + 1], ph, &vh[2]);
                mma16816(acc_o[2 * np + 1], ph, &vl[2]);
                mma16816(acc_o[2 * np + 1], pl, &vh[2]);
            }
        }
        __syncthreads();
    }

    // ---- finalize ----
    l0 += __shfl_xor_sync(0xffffffff, l0, 1);
    l0 += __shfl_xor_sync(0xffffffff, l0, 2);
    l1 += __shfl_xor_sync(0xffffffff, l1, 1);
    l1 += __shfl_xor_sync(0xffffffff, l1, 2);
    float inv0 = 1.f / l0;
    float inv1 = 1.f / l1;

    const size_t row0 = (size_t)(b * T_ + q0) * C_ + h * 64;
    const size_t row1 = (size_t)(b * T_ + q1) * C_ + h * 64;
    #pragma unroll
    for (int j = 0; j < 8; j++) {
        int d = 8 * j + 2 * (lane & 3);
        uint32_t hi, lo;
        split2(acc_o[j][0] * inv0, acc_o[j][1] * inv0, hi, lo);
        *(uint32_t*)(g_yhi + row0 + d) = hi;
        *(uint32_t*)(g_ylo + row0 + d) = lo;
        split2(acc_o[j][2] * inv1, acc_o[j][3] * inv1, hi, lo);
        *(uint32_t*)(g_yhi + row1 + d) = hi;
        *(uint32_t*)(g_ylo + row1 + d) = lo;
    }
}

// ---------------- launch ---------------------------------------------------
extern "C" void kernel_launch(void* const* d_in, const int* in_sizes, int n_in,
                              void* d_out, int out_size)
{
    const float* x  = (const float*)d_in[0];
    const float* wq = (const float*)d_in[1];
    const float* bq = (const float*)d_in[2];
    const float* wk = (const float*)d_in[3];
    const float* bk = (const float*)d_in[4];
    const float* wv = (const float*)d_in[5];
    const float* bv = (const float*)d_in[6];
    const float* wp = (const float*)d_in[7];
    const float* bp = (const float*)d_in[8];
    float* out = (float*)d_out;

    static bool attr_done = false;
    if (!attr_done) {
        cudaFuncSetAttribute(qkv_mma_kernel,
                             cudaFuncAttributeMaxDynamicSharedMemorySize, SMEM_BYTES);
        cudaFuncSetAttribute(proj_mma_kernel,
                             cudaFuncAttributeMaxDynamicSharedMemorySize, SMEM_BYTES);
        cudaFuncSetAttribute(attn_mma_kernel,
                             cudaFuncAttributeMaxDynamicSharedMemorySize, ATT_SMEM);
        attr_done = true;
    }

    rope_init_kernel<<<(T_ * HALF_ + 255) / 256, 256>>>();

    const int nsplit = M_ * C_ / 4 + 4 * (C_ * C_ / 4);
    split_all_kernel<<<(nsplit + 255) / 256, 256>>>(x, wq, wk, wv, wp);

    qkv_mma_kernel<<<dim3(M_ / 128, C_ / 128, 3), 256, SMEM_BYTES>>>(bq, bk, bv);
    attn_mma_kernel<<<dim3(T_ / 128, H_, B_), 256, ATT_SMEM>>>();
    proj_mma_kernel<<<dim3(M_ / 128, C_ / 128), 256, SMEM_BYTES>>>(bp, out);
}

// round 7
// speedup vs baseline: 4.0998x; 1.0002x over previous
#include <cuda_runtime.h>
#include <cuda_bf16.h>
#include <math.h>
#include <stdint.h>

#define B_ 4
#define T_ 2048
#define C_ 1024
#define H_ 16
#define D_ 64
#define M_ (B_ * T_)          // 8192 rows
#define HALF_ 32              // D/2 for RoPE
#define NCH32_ (C_ / 32)      // 32 K-chunks of 32 bf16

// ---------------- scratch (device globals: no runtime allocation) ----------
__device__ float g_cos[T_ * HALF_];
__device__ float g_sin[T_ * HALF_];
__device__ __nv_bfloat16 g_xhi[(size_t)M_ * C_];
__device__ __nv_bfloat16 g_xlo[(size_t)M_ * C_];
__device__ __nv_bfloat16 g_whi[(size_t)4 * C_ * C_];   // wq,wk,wv,wp
__device__ __nv_bfloat16 g_wlo[(size_t)4 * C_ * C_];
__device__ __nv_bfloat16 g_yhi[(size_t)M_ * C_];
__device__ __nv_bfloat16 g_ylo[(size_t)M_ * C_];
__device__ __nv_bfloat16 g_qhi[(size_t)B_ * H_ * T_ * D_];
__device__ __nv_bfloat16 g_qlo[(size_t)B_ * H_ * T_ * D_];
__device__ __nv_bfloat16 g_khi[(size_t)B_ * H_ * T_ * D_];
__device__ __nv_bfloat16 g_klo[(size_t)B_ * H_ * T_ * D_];
__device__ __nv_bfloat16 g_vhi[(size_t)B_ * H_ * T_ * D_];
__device__ __nv_bfloat16 g_vlo[(size_t)B_ * H_ * T_ * D_];

// ---------------- PTX helpers (portable: sm_80+ features only) -------------
__device__ __forceinline__ uint32_t smem_u32(const void* p) {
    uint32_t a;
    asm("{ .reg .u64 t; cvta.to.shared.u64 t, %1; cvt.u32.u64 %0, t; }"
        : "=r"(a) : "l"(p));
    return a;
}

__device__ __forceinline__ void cp16(uint32_t saddr, const void* g) {
    asm volatile("cp.async.cg.shared.global [%0], [%1], 16;" :: "r"(saddr), "l"(g));
}
__device__ __forceinline__ void cp_commit() {
    asm volatile("cp.async.commit_group;" ::: "memory");
}
template <int N> __device__ __forceinline__ void cp_wait() {
    asm volatile("cp.async.wait_group %0;" :: "n"(N) : "memory");
}

__device__ __forceinline__ void ldsm_x4(uint32_t addr, uint32_t* r) {
    asm volatile("ldmatrix.sync.aligned.m8n8.x4.shared.b16 {%0,%1,%2,%3}, [%4];"
        : "=r"(r[0]), "=r"(r[1]), "=r"(r[2]), "=r"(r[3]) : "r"(addr));
}

__device__ __forceinline__ void ldsm_x4_trans(uint32_t addr, uint32_t* r) {
    asm volatile("ldmatrix.sync.aligned.m8n8.x4.trans.shared.b16 {%0,%1,%2,%3}, [%4];"
        : "=r"(r[0]), "=r"(r[1]), "=r"(r[2]), "=r"(r[3]) : "r"(addr));
}

__device__ __forceinline__ void mma16816(float* d, const uint32_t* a, const uint32_t* b) {
    asm volatile(
        "mma.sync.aligned.m16n8k16.row.col.f32.bf16.bf16.f32 "
        "{%0,%1,%2,%3}, {%4,%5,%6,%7}, {%8,%9}, {%0,%1,%2,%3};"
        : "+f"(d[0]), "+f"(d[1]), "+f"(d[2]), "+f"(d[3])
        : "r"(a[0]), "r"(a[1]), "r"(a[2]), "r"(a[3]), "r"(b[0]), "r"(b[1]));
}

__device__ __forceinline__ void split2(float a, float b, uint32_t& hi, uint32_t& lo) {
    __nv_bfloat16 h0 = __float2bfloat16(a);
    __nv_bfloat16 h1 = __float2bfloat16(b);
    __nv_bfloat16 l0 = __float2bfloat16(a - __bfloat162float(h0));
    __nv_bfloat16 l1 = __float2bfloat16(b - __bfloat162float(h1));
    __nv_bfloat162 H = __halves2bfloat162(h0, h1);
    __nv_bfloat162 L = __halves2bfloat162(l0, l1);
    hi = *(uint32_t*)&H;
    lo = *(uint32_t*)&L;
}

// ---------------- smem layout (GEMM) ---------------------------------------
// K=32 chunks. Stage (32KB) at s*32768:
//   A rows at +0     : 128 rows x 128B = [Ahi 64B | Alo 64B]  (cb 0..3 hi, 4..7 lo)
//   B rows at +16384 : 128 rows x 128B = [Bhi 64B | Blo 64B]
#define GSTG_ 32768
#define CS_LD 132
#define SMEM_BYTES (128 * CS_LD * 4)    // 67584 >= 2*GSTG_ (65536)

// ---------------- RoPE table -----------------------------------------------
__global__ void rope_init_kernel() {
    int idx = blockIdx.x * blockDim.x + threadIdx.x;
    if (idx >= T_ * HALF_) return;
    int t = idx / HALF_;
    int i = idx % HALF_;
    double alpha = pow(10000.0, -(double)i / (double)HALF_);
    double ang = (double)t * alpha;
    g_cos[idx] = (float)cos(ang);
    g_sin[idx] = (float)sin(ang);
}

// ---------------- fused fp32 -> bf16 hi/lo split (x + 4 weights) -----------
__global__ __launch_bounds__(256) void split_all_kernel(
    const float* __restrict__ x, const float* __restrict__ wq,
    const float* __restrict__ wk, const float* __restrict__ wv,
    const float* __restrict__ wp)
{
    const int NX = M_ * C_ / 4;
    const int NW = C_ * C_ / 4;
    int i = blockIdx.x * blockDim.x + threadIdx.x;
    if (i >= NX + 4 * NW) return;

    const float* src;
    __nv_bfloat16 *hi, *lo;
    int off;
    if (i < NX) {
        src = x; hi = g_xhi; lo = g_xlo; off = i;
    } else {
        int j = i - NX;
        int w = j >> 18;
        off = j & (NW - 1);
        src = (w == 0) ? wq : (w == 1) ? wk : (w == 2) ? wv : wp;
        hi = g_whi + (size_t)w * C_ * C_;
        lo = g_wlo + (size_t)w * C_ * C_;
    }
    float4 v = ((const float4*)src)[off];
    uint32_t h0, l0, h1, l1;
    split2(v.x, v.y, h0, l0);
    split2(v.z, v.w, h1, l1);
    ((uint32_t*)hi)[2 * off + 0] = h0;
    ((uint32_t*)hi)[2 * off + 1] = h1;
    ((uint32_t*)lo)[2 * off + 0] = l0;
    ((uint32_t*)lo)[2 * off + 1] = l1;
}

// ---------------- pipelined mma.sync GEMM (K=32 chunks, 2-stage) -----------
__device__ __forceinline__ void gemm_issue_chunk(
    const __nv_bfloat16* __restrict__ Ahi, const __nv_bfloat16* __restrict__ Alo,
    const __nv_bfloat16* __restrict__ Bhi, const __nv_bfloat16* __restrict__ Blo,
    int m0, int n0, int kc, uint32_t sb)
{
    const int tid = threadIdx.x;
    const int k0 = kc * 32;
    #pragma unroll
    for (int it = 0; it < 8; it++) {
        int idx = tid + it * 256;         // 0..2047 16B transfers
        int sel = idx >> 10;              // 0=A, 1=B
        int sub = idx & 1023;
        int r = sub >> 3;                 // 0..127
        int cb = sub & 7;                 // 0..3 hi, 4..7 lo
        uint32_t off = (uint32_t)(r * 128 + cb * 16);
        uint32_t sw = off ^ (uint32_t)((r & 7) << 4);
        const __nv_bfloat16* src = sel ? ((cb < 4) ? Bhi : Blo)
                                       : ((cb < 4) ? Ahi : Alo);
        int row = (sel ? n0 : m0) + r;
        size_t g = (size_t)row * C_ + k0 + (cb & 3) * 8;
        cp16(sb + sel * 16384 + sw, src + g);
    }
    cp_commit();
}

__device__ __forceinline__ void gemm_mma(
    const __nv_bfloat16* __restrict__ Ahi, const __nv_bfloat16* __restrict__ Alo,
    const __nv_bfloat16* __restrict__ Bhi, const __nv_bfloat16* __restrict__ Blo,
    int m0, int n0, char* smem, float acc[4][4][4])
{
    const int tid = threadIdx.x;
    const int wid = tid >> 5;
    const int lane = tid & 31;
    const int wm = wid >> 2;
    const int wn = wid & 3;
    const uint32_t sbase = smem_u32(smem);

    #pragma unroll
    for (int mi = 0; mi < 4; mi++)
        #pragma unroll
        for (int nj = 0; nj < 4; nj++)
            #pragma unroll
            for (int e = 0; e < 4; e++) acc[mi][nj][e] = 0.f;

    const int a_row = lane & 15;
    const int a_kh  = lane >> 4;
    const int bg    = lane >> 3;
    const int b_row = ((bg >> 1) << 3) + (lane & 7);
    const int b_kh  = bg & 1;

    gemm_issue_chunk(Ahi, Alo, Bhi, Blo, m0, n0, 0, sbase);

    for (int kc = 0; kc < NCH32_; kc++) {
        if (kc + 1 < NCH32_) {
            gemm_issue_chunk(Ahi, Alo, Bhi, Blo, m0, n0, kc + 1,
                             sbase + ((kc + 1) & 1) * GSTG_);
            cp_wait<1>();
        } else {
            cp_wait<0>();
        }
        __syncthreads();

        const uint32_t st = sbase + (kc & 1) * GSTG_;
        #pragma unroll
        for (int kk = 0; kk < 2; kk++) {
            uint32_t bh[4][2], bl[4][2];
            #pragma unroll
            for (int np = 0; np < 2; np++) {
                int R = wn * 32 + np * 16 + b_row;
                int cbh = kk * 2 + b_kh;
                uint32_t offh = (uint32_t)(R * 128 + cbh * 16);
                uint32_t offl = (uint32_t)(R * 128 + (cbh + 4) * 16);
                uint32_t swm = (uint32_t)((R & 7) << 4);
                ldsm_x4(st + 16384 + (offh ^ swm), &bh[np * 2][0]);
                ldsm_x4(st + 16384 + (offl ^ swm), &bl[np * 2][0]);
            }
            #pragma unroll
            for (int mi = 0; mi < 4; mi++) {
                uint32_t ah[4], al[4];
                int R = wm * 64 + mi * 16 + a_row;
                int cbh = kk * 2 + a_kh;
                uint32_t offh = (uint32_t)(R * 128 + cbh * 16);
                uint32_t offl = (uint32_t)(R * 128 + (cbh + 4) * 16);
                uint32_t swm = (uint32_t)((R & 7) << 4);
                ldsm_x4(st + (offh ^ swm), ah);
                ldsm_x4(st + (offl ^ swm), al);
                #pragma unroll
                for (int nj = 0; nj < 4; nj++) {
                    mma16816(acc[mi][nj], ah, bh[nj]);
                    mma16816(acc[mi][nj], ah, bl[nj]);
                    mma16816(acc[mi][nj], al, bh[nj]);
                }
            }
        }
        __syncthreads();
    }
}

__device__ __forceinline__ void acc_to_smem(
    float acc[4][4][4], char* smem, const float* __restrict__ bias, int n0)
{
    float* Cs = (float*)smem;
    const int wid = threadIdx.x >> 5;
    const int lane = threadIdx.x & 31;
    const int wm = wid >> 2, wn = wid & 3;
    const int r0 = wm * 64 + (lane >> 2);
    const int c0 = wn * 32 + 2 * (lane & 3);
    #pragma unroll
    for (int mi = 0; mi < 4; mi++) {
        #pragma unroll
        for (int nj = 0; nj < 4; nj++) {
            int r = r0 + mi * 16;
            int c = c0 + nj * 8;
            float b0 = __ldg(&bias[n0 + c]);
            float b1 = __ldg(&bias[n0 + c + 1]);
            Cs[r * CS_LD + c]           = acc[mi][nj][0] + b0;
            Cs[r * CS_LD + c + 1]       = acc[mi][nj][1] + b1;
            Cs[(r + 8) * CS_LD + c]     = acc[mi][nj][2] + b0;
            Cs[(r + 8) * CS_LD + c + 1] = acc[mi][nj][3] + b1;
        }
    }
}

// ---------------- QKV GEMM + bias + RoPE + hi/lo split epilogue ------------
__global__ __launch_bounds__(256, 2) void qkv_mma_kernel(
    const float* __restrict__ bq, const float* __restrict__ bk,
    const float* __restrict__ bv)
{
    extern __shared__ __align__(16) char smem[];
    const int z = blockIdx.z;
    const __nv_bfloat16* Whi = g_whi + (size_t)z * C_ * C_;
    const __nv_bfloat16* Wlo = g_wlo + (size_t)z * C_ * C_;
    const float* bias = (z == 0) ? bq : (z == 1) ? bk : bv;

    const int m0 = blockIdx.x * 128;
    const int n0 = blockIdx.y * 128;

    float acc[4][4][4];
    gemm_mma(g_xhi, g_xlo, Whi, Wlo, m0, n0, smem, acc);
    acc_to_smem(acc, smem, bias, n0);
    __syncthreads();

    const float* Cs = (const float*)smem;
    const int tid = threadIdx.x;
    const int b = m0 / T_;
    const int tbase = m0 % T_;

    if (z < 2) {
        __nv_bfloat16* dHi = (z == 0) ? g_qhi : g_khi;
        __nv_bfloat16* dLo = (z == 0) ? g_qlo : g_klo;
        #pragma unroll
        for (int it = 0; it < 32; it++) {
            int p = tid + it * 256;
            int row = p >> 6;
            int q6 = p & 63;
            int hd = q6 >> 5;
            int i = q6 & 31;
            int t = tbase + row;
            int h = (n0 >> 6) + hd;
            float xr = Cs[row * CS_LD + hd * 64 + i];
            float xi = Cs[row * CS_LD + hd * 64 + i + 32];
            float cs = g_cos[t * HALF_ + i];
            float sn = g_sin[t * HALF_ + i];
            float a = xr * cs - xi * sn;
            float c = xr * sn + xi * cs;
            size_t base = ((size_t)(b * H_ + h) * T_ + t) * D_;
            __nv_bfloat16 ah = __float2bfloat16(a);
            __nv_bfloat16 ch = __float2bfloat16(c);
            dHi[base + i]      = ah;
            dHi[base + i + 32] = ch;
            dLo[base + i]      = __float2bfloat16(a - __bfloat162float(ah));
            dLo[base + i + 32] = __float2bfloat16(c - __bfloat162float(ch));
        }
    } else {
        #pragma unroll
        for (int it = 0; it < 16; it++) {
            int e = tid + it * 256;
            int row = e >> 5;
            int col = (e & 31) * 4;
            int hd = col >> 6;
            int d = col & 63;
            int t = tbase + row;
            int h = (n0 >> 6) + hd;
            float4 v4 = *(const float4*)&Cs[row * CS_LD + col];
            uint32_t h0, l0, h1, l1;
            split2(v4.x, v4.y, h0, l0);
            split2(v4.z, v4.w, h1, l1);
            size_t base = ((size_t)(b * H_ + h) * T_ + t) * D_ + d;
            ((uint32_t*)(g_vhi + base))[0] = h0;
            ((uint32_t*)(g_vhi + base))[1] = h1;
            ((uint32_t*)(g_vlo + base))[0] = l0;
            ((uint32_t*)(g_vlo + base))[1] = l1;
        }
    }
}

// ---------------- output projection GEMM -----------------------------------
__global__ __launch_bounds__(256, 2) void proj_mma_kernel(
    const float* __restrict__ bp, float* __restrict__ out)
{
    extern __shared__ __align__(16) char smem[];
    const int m0 = blockIdx.x * 128;
    const int n0 = blockIdx.y * 128;
    const __nv_bfloat16* Whi = g_whi + (size_t)3 * C_ * C_;
    const __nv_bfloat16* Wlo = g_wlo + (size_t)3 * C_ * C_;

    float acc[4][4][4];
    gemm_mma(g_yhi, g_ylo, Whi, Wlo, m0, n0, smem, acc);
    acc_to_smem(acc, smem, bp, n0);
    __syncthreads();

    const float* Cs = (const float*)smem;
    const int tid = threadIdx.x;
    #pragma unroll
    for (int it = 0; it < 16; it++) {
        int e = tid + it * 256;
        int row = e >> 5;
        int col = (e & 31) * 4;
        float4 v4 = *(const float4*)&Cs[row * CS_LD + col];
        *(float4*)&out[(size_t)(m0 + row) * C_ + n0 + col] = v4;
    }
}

// ---------------- mma.sync causal flash attention (pipelined K/V) ----------
// grid (T/128, H, B), 256 threads; K/V tiles of 64 in two 32KB stages.
// stage s at s*32768: K_HI +0, K_LO +8192, V_HI +16384, V_LO +24576
#define ASTG_ 32768
#define ATT_SMEM (2 * ASTG_)

__device__ __forceinline__ void attn_issue_tile(
    const __nv_bfloat16* __restrict__ Khi, const __nv_bfloat16* __restrict__ Klo,
    const __nv_bfloat16* __restrict__ Vhi, const __nv_bfloat16* __restrict__ Vlo,
    int ti, uint32_t sb)
{
    const int tid = threadIdx.x;
    #pragma unroll
    for (int it = 0; it < 8; it++) {
        int idx = tid + it * 256;
        int sel = idx >> 9;
        int sub = idx & 511;
        int r = sub >> 3;
        int cb = sub & 7;
        uint32_t off = (uint32_t)(r * 128 + cb * 16);
        uint32_t sw = off ^ (uint32_t)((r & 7) << 4);
        size_t g = (size_t)(ti * 64 + r) * D_ + cb * 8;
        const __nv_bfloat16* src = (sel == 0) ? Khi : (sel == 1) ? Klo
                                  : (sel == 2) ? Vhi : Vlo;
        cp16(sb + sel * 8192 + sw, src + g);
    }
    cp_commit();
}

__global__ __launch_bounds__(256, 2) void attn_mma_kernel() {
    extern __shared__ __align__(16) char smem[];
    const uint32_t sbase = smem_u32(smem);
    const int tid = threadIdx.x;
    const int w = tid >> 5;
    const int lane = tid & 31;
    const int bx = blockIdx.x;
    const int h = blockIdx.y;
    const int b = blockIdx.z;

    const size_t head = (size_t)(b * H_ + h) * T_ * D_;
    const __nv_bfloat16* Qhi = g_qhi + head;
    const __nv_bfloat16* Qlo = g_qlo + head;
    const __nv_bfloat16* Khi = g_khi + head;
    const __nv_bfloat16* Klo = g_klo + head;
    const __nv_bfloat16* Vhi = g_vhi + head;
    const __nv_bfloat16* Vlo = g_vlo + head;

    // ---- stage Q into stage0 region, load per-warp A fragments ----
    #pragma unroll
    for (int it = 0; it < 4; it++) {
        int idx = tid + it * 256;
        int r = idx >> 3;
        int cb = idx & 7;
        uint32_t off = (uint32_t)(r * 128 + cb * 16);
        uint32_t sw = off ^ (uint32_t)((r & 7) << 4);
        size_t g = (size_t)(bx * 128 + r) * D_ + cb * 8;
        *(uint4*)(smem + sw)         = *(const uint4*)(Qhi + g);
        *(uint4*)(smem + 16384 + sw) = *(const uint4*)(Qlo + g);
    }
    __syncthreads();

    uint32_t qh[4][4], ql[4][4];
    {
        const int a_row = lane & 15;
        const int a_kh = lane >> 4;
        #pragma unroll
        for (int kt = 0; kt < 4; kt++) {
            int R = w * 16 + a_row;
            int cb = kt * 2 + a_kh;
            uint32_t off = (uint32_t)(R * 128 + cb * 16);
            uint32_t sw = off ^ (uint32_t)((R & 7) << 4);
            ldsm_x4(sbase + sw, qh[kt]);
            ldsm_x4(sbase + 16384 + sw, ql[kt]);
        }
    }
    __syncthreads();

    const int q0 = bx * 128 + w * 16 + (lane >> 2);
    const int q1 = q0 + 8;
    float m0 = -INFINITY, m1 = -INFINITY, l0 = 0.f, l1 = 0.f;
    float acc_o[8][4];
    #pragma unroll
    for (int j = 0; j < 8; j++)
        #pragma unroll
        for (int e = 0; e < 4; e++) acc_o[j][e] = 0.f;

    const float S2 = 0.125f * 1.44269504088896f;

    const int bg = lane >> 3;
    const int b_row = ((bg >> 1) << 3) + (lane & 7);
    const int b_kh = bg & 1;
    const int l7 = lane & 7;
    const int ntiles = 2 * bx + 2;

    attn_issue_tile(Khi, Klo, Vhi, Vlo, 0, sbase);

    for (int ti = 0; ti < ntiles; ti++) {
        if (ti + 1 < ntiles) {
            attn_issue_tile(Khi, Klo, Vhi, Vlo, ti + 1,
                            sbase + ((ti + 1) & 1) * ASTG_);
            cp_wait<1>();
        } else {
            cp_wait<0>();
        }
        __syncthreads();

        const uint32_t st = sbase + (ti & 1) * ASTG_;

        float acc[8][4];
        #pragma unroll
        for (int j = 0; j < 8; j++)
            #pragma unroll
            for (int e = 0; e < 4; e++) acc[j][e] = 0.f;

        #pragma unroll
        for (int kt = 0; kt < 4; kt++) {
            uint32_t bh[8][2], bl[8][2];
            #pragma unroll
            for (int np = 0; np < 4; np++) {
                int R = np * 16 + b_row;
                int cb = kt * 2 + b_kh;
                uint32_t off = (uint32_t)(R * 128 + cb * 16);
                uint32_t sw = off ^ (uint32_t)((R & 7) << 4);
                ldsm_x4(st + sw, &bh[np * 2][0]);
                ldsm_x4(st + 8192 + sw, &bl[np * 2][0]);
            }
            #pragma unroll
            for (int j = 0; j < 8; j++) {
                mma16816(acc[j], qh[kt], bh[j]);
                mma16816(acc[j], qh[kt], bl[j]);
                mma16816(acc[j], ql[kt], bh[j]);
            }
        }

        if (ti >= 2 * bx) {
            #pragma unroll
            for (int j = 0; j < 8; j++) {
                int s0 = ti * 64 + 8 * j + 2 * (lane & 3);
                if (s0     > q0) acc[j][0] = -INFINITY;
                if (s0 + 1 > q0) acc[j][1] = -INFINITY;
                if (s0     > q1) acc[j][2] = -INFINITY;
                if (s0 + 1 > q1) acc[j][3] = -INFINITY;
            }
        }

        float mt0 = -INFINITY, mt1 = -INFINITY;
        #pragma unroll
        for (int j = 0; j < 8; j++) {
            mt0 = fmaxf(mt0, fmaxf(acc[j][0], acc[j][1]));
            mt1 = fmaxf(mt1, fmaxf(acc[j][2], acc[j][3]));
        }
        mt0 = fmaxf(mt0, __shfl_xor_sync(0xffffffff, mt0, 1));
        mt0 = fmaxf(mt0, __shfl_xor_sync(0xffffffff, mt0, 2));
        mt1 = fmaxf(mt1, __shfl_xor_sync(0xffffffff, mt1, 1));
        mt1 = fmaxf(mt1, __shfl_xor_sync(0xffffffff, mt1, 2));

        float mn0 = fmaxf(m0, mt0);
        float mn1 = fmaxf(m1, mt1);
        float c0 = exp2f((m0 - mn0) * S2);
        float c1 = exp2f((m1 - mn1) * S2);
        l0 *= c0; l1 *= c1;
        #pragma unroll
        for (int j = 0; j < 8; j++) {
            acc_o[j][0] *= c0; acc_o[j][1] *= c0;
            acc_o[j][2] *= c1; acc_o[j][3] *= c1;
        }
        float fm0 = mn0 * S2, fm1 = mn1 * S2;
        #pragma unroll
        for (int j = 0; j < 8; j++) {
            float p0 = exp2f(acc[j][0] * S2 - fm0);
            float p1 = exp2f(acc[j][1] * S2 - fm0);
            float p2 = exp2f(acc[j][2] * S2 - fm1);
            float p3 = exp2f(acc[j][3] * S2 - fm1);
            l0 += p0 + p1;
            l1 += p2 + p3;
            acc[j][0] = p0; acc[j][1] = p1; acc[j][2] = p2; acc[j][3] = p3;
        }
        m0 = mn0; m1 = mn1;

        #pragma unroll
        for (int kt = 0; kt < 4; kt++) {
            uint32_t ph[4], pl[4];
            split2(acc[2 * kt][0],     acc[2 * kt][1],     ph[0], pl[0]);
            split2(acc[2 * kt][2],     acc[2 * kt][3],     ph[1], pl[1]);
            split2(acc[2 * kt + 1][0], acc[2 * kt + 1][1], ph[2], pl[2]);
            split2(acc[2 * kt + 1][2], acc[2 * kt + 1][3], ph[3], pl[3]);
            #pragma unroll
            for (int np = 0; np < 4; np++) {
                int srow = kt * 16 + ((bg & 1) << 3) + l7;
                int dcol = np * 16 + ((bg >> 1) << 3);
                uint32_t off = (uint32_t)(srow * 128 + dcol * 2);
                uint32_t sw = off ^ (uint32_t)((srow & 7) << 4);
                uint32_t vh[4], vl[4];
                ldsm_x4_trans(st + 16384 + sw, vh);
                ldsm_x4_trans(st + 24576 + sw, vl);
                mma16816(acc_o[2 * np],     ph, &vh[0]);
                mma16816(acc_o[2 * np],     ph, &vl[0]);
                mma16816(acc_o[2 * np],     pl, &vh[0]);
                mma16816(acc_o[2 * np + 1], ph, &vh[2]);
                mma16816(acc_o[2 * np + 1], ph, &vl[2]);
                mma16816(acc_o[2 * np + 1], pl, &vh[2]);
            }
        }
        __syncthreads();
    }

    l0 += __shfl_xor_sync(0xffffffff, l0, 1);
    l0 += __shfl_xor_sync(0xffffffff, l0, 2);
    l1 += __shfl_xor_sync(0xffffffff, l1, 1);
    l1 += __shfl_xor_sync(0xffffffff, l1, 2);
    float inv0 = 1.f / l0;
    float inv1 = 1.f / l1;

    const size_t row0 = (size_t)(b * T_ + q0) * C_ + h * 64;
    const size_t row1 = (size_t)(b * T_ + q1) * C_ + h * 64;
    #pragma unroll
    for (int j = 0; j < 8; j++) {
        int d = 8 * j + 2 * (lane & 3);
        uint32_t hi, lo;
        split2(acc_o[j][0] * inv0, acc_o[j][1] * inv0, hi, lo);
        *(uint32_t*)(g_yhi + row0 + d) = hi;
        *(uint32_t*)(g_ylo + row0 + d) = lo;
        split2(acc_o[j][2] * inv1, acc_o[j][3] * inv1, hi, lo);
        *(uint32_t*)(g_yhi + row1 + d) = hi;
        *(uint32_t*)(g_ylo + row1 + d) = lo;
    }
}

// ---------------- launch ---------------------------------------------------
extern "C" void kernel_launch(void* const* d_in, const int* in_sizes, int n_in,
                              void* d_out, int out_size)
{
    const float* x  = (const float*)d_in[0];
    const float* wq = (const float*)d_in[1];
    const float* bq = (const float*)d_in[2];
    const float* wk = (const float*)d_in[3];
    const float* bk = (const float*)d_in[4];
    const float* wv = (const float*)d_in[5];
    const float* bv = (const float*)d_in[6];
    const float* wp = (const float*)d_in[7];
    const float* bp = (const float*)d_in[8];
    float* out = (float*)d_out;

    static bool attr_done = false;
    if (!attr_done) {
        cudaFuncSetAttribute(qkv_mma_kernel,
                             cudaFuncAttributeMaxDynamicSharedMemorySize, SMEM_BYTES);
        cudaFuncSetAttribute(proj_mma_kernel,
                             cudaFuncAttributeMaxDynamicSharedMemorySize, SMEM_BYTES);
        cudaFuncSetAttribute(attn_mma_kernel,
                             cudaFuncAttributeMaxDynamicSharedMemorySize, ATT_SMEM);
        attr_done = true;
    }

    rope_init_kernel<<<(T_ * HALF_ + 255) / 256, 256>>>();

    const int nsplit = M_ * C_ / 4 + 4 * (C_ * C_ / 4);
    split_all_kernel<<<(nsplit + 255) / 256, 256>>>(x, wq, wk, wv, wp);

    qkv_mma_kernel<<<dim3(M_ / 128, C_ / 128, 3), 256, SMEM_BYTES>>>(bq, bk, bv);
    attn_mma_kernel<<<dim3(T_ / 128, H_, B_), 256, ATT_SMEM>>>();
    proj_mma_kernel<<<dim3(M_ / 128, C_ / 128), 256, SMEM_BYTES>>>(bp, out);
}

// round 9
// speedup vs baseline: 4.1451x; 1.0110x over previous
#include <cuda_runtime.h>
#include <cuda_bf16.h>
#include <math.h>
#include <stdint.h>

#define B_ 4
#define T_ 2048
#define C_ 1024
#define H_ 16
#define D_ 64
#define M_ (B_ * T_)          // 8192 rows
#define HALF_ 32              // D/2 for RoPE
#define NCH32_ (C_ / 32)      // 32 K-chunks of 32 bf16

// ---------------- scratch (device globals: no runtime allocation) ----------
__device__ float g_cos[T_ * HALF_];
__device__ float g_sin[T_ * HALF_];
__device__ __nv_bfloat16 g_xhi[(size_t)M_ * C_];
__device__ __nv_bfloat16 g_xlo[(size_t)M_ * C_];
__device__ __nv_bfloat16 g_whi[(size_t)4 * C_ * C_];   // wq,wk,wv,wp
__device__ __nv_bfloat16 g_wlo[(size_t)4 * C_ * C_];
__device__ __nv_bfloat16 g_yhi[(size_t)M_ * C_];
__device__ __nv_bfloat16 g_ylo[(size_t)M_ * C_];
__device__ __nv_bfloat16 g_qhi[(size_t)B_ * H_ * T_ * D_];
__device__ __nv_bfloat16 g_qlo[(size_t)B_ * H_ * T_ * D_];
__device__ __nv_bfloat16 g_khi[(size_t)B_ * H_ * T_ * D_];
__device__ __nv_bfloat16 g_klo[(size_t)B_ * H_ * T_ * D_];
__device__ __nv_bfloat16 g_vhi[(size_t)B_ * H_ * T_ * D_];
__device__ __nv_bfloat16 g_vlo[(size_t)B_ * H_ * T_ * D_];

// ---------------- PTX helpers (portable: sm_80+ features only) -------------
__device__ __forceinline__ uint32_t smem_u32(const void* p) {
    uint32_t a;
    asm("{ .reg .u64 t; cvta.to.shared.u64 t, %1; cvt.u32.u64 %0, t; }"
        : "=r"(a) : "l"(p));
    return a;
}

__device__ __forceinline__ void cp16(uint32_t saddr, const void* g) {
    asm volatile("cp.async.cg.shared.global [%0], [%1], 16;" :: "r"(saddr), "l"(g));
}
__device__ __forceinline__ void cp_commit() {
    asm volatile("cp.async.commit_group;" ::: "memory");
}
template <int N> __device__ __forceinline__ void cp_wait() {
    asm volatile("cp.async.wait_group %0;" :: "n"(N) : "memory");
}

#define BARG(id) asm volatile("bar.sync %0, 128;" :: "r"(id) : "memory")

__device__ __forceinline__ void ldsm_x4(uint32_t addr, uint32_t* r) {
    asm volatile("ldmatrix.sync.aligned.m8n8.x4.shared.b16 {%0,%1,%2,%3}, [%4];"
        : "=r"(r[0]), "=r"(r[1]), "=r"(r[2]), "=r"(r[3]) : "r"(addr));
}

__device__ __forceinline__ void ldsm_x4_trans(uint32_t addr, uint32_t* r) {
    asm volatile("ldmatrix.sync.aligned.m8n8.x4.trans.shared.b16 {%0,%1,%2,%3}, [%4];"
        : "=r"(r[0]), "=r"(r[1]), "=r"(r[2]), "=r"(r[3]) : "r"(addr));
}

__device__ __forceinline__ void mma16816(float* d, const uint32_t* a, const uint32_t* b) {
    asm volatile(
        "mma.sync.aligned.m16n8k16.row.col.f32.bf16.bf16.f32 "
        "{%0,%1,%2,%3}, {%4,%5,%6,%7}, {%8,%9}, {%0,%1,%2,%3};"
        : "+f"(d[0]), "+f"(d[1]), "+f"(d[2]), "+f"(d[3])
        : "r"(a[0]), "r"(a[1]), "r"(a[2]), "r"(a[3]), "r"(b[0]), "r"(b[1]));
}

// cheap hi/lo split: hi = truncate-to-bf16 (exact, via PRMT), lo = rn(x - hi)
__device__ __forceinline__ void split2(float a, float b, uint32_t& hi, uint32_t& lo) {
    uint32_t ua = __float_as_uint(a), ub = __float_as_uint(b);
    uint32_t h;
    asm("prmt.b32 %0, %1, %2, 0x7632;" : "=r"(h) : "r"(ua), "r"(ub));
    float fa = __uint_as_float(ua & 0xFFFF0000u);
    float fb = __uint_as_float(ub & 0xFFFF0000u);
    uint32_t l;
    asm("cvt.rn.bf16x2.f32 %0, %1, %2;" : "=r"(l) : "f"(b - fb), "f"(a - fa));
    hi = h;
    lo = l;
}

// ---------------- smem layout (GEMM) ---------------------------------------
#define GSTG_ 32768
#define CS_LD 132
#define SMEM_BYTES (128 * CS_LD * 4)    // 67584 >= 2*GSTG_ (65536)

// ---------------- RoPE table -----------------------------------------------
__global__ void rope_init_kernel() {
    int idx = blockIdx.x * blockDim.x + threadIdx.x;
    if (idx >= T_ * HALF_) return;
    int t = idx / HALF_;
    int i = idx % HALF_;
    double alpha = pow(10000.0, -(double)i / (double)HALF_);
    double ang = (double)t * alpha;
    g_cos[idx] = (float)cos(ang);
    g_sin[idx] = (float)sin(ang);
}

// ---------------- fused fp32 -> bf16 hi/lo split (x + 4 weights) -----------
__global__ __launch_bounds__(256) void split_all_kernel(
    const float* __restrict__ x, const float* __restrict__ wq,
    const float* __restrict__ wk, const float* __restrict__ wv,
    const float* __restrict__ wp)
{
    const int NX = M_ * C_ / 4;
    const int NW = C_ * C_ / 4;
    int i = blockIdx.x * blockDim.x + threadIdx.x;
    if (i >= NX + 4 * NW) return;

    const float* src;
    __nv_bfloat16 *hi, *lo;
    int off;
    if (i < NX) {
        src = x; hi = g_xhi; lo = g_xlo; off = i;
    } else {
        int j = i - NX;
        int w = j >> 18;
        off = j & (NW - 1);
        src = (w == 0) ? wq : (w == 1) ? wk : (w == 2) ? wv : wp;
        hi = g_whi + (size_t)w * C_ * C_;
        lo = g_wlo + (size_t)w * C_ * C_;
    }
    float4 v = ((const float4*)src)[off];
    uint32_t h0, l0, h1, l1;
    split2(v.x, v.y, h0, l0);
    split2(v.z, v.w, h1, l1);
    ((uint32_t*)hi)[2 * off + 0] = h0;
    ((uint32_t*)hi)[2 * off + 1] = h1;
    ((uint32_t*)lo)[2 * off + 0] = l0;
    ((uint32_t*)lo)[2 * off + 1] = l1;
}

// ---------------- pipelined mma.sync GEMM (K=32 chunks, 2-stage) -----------
__device__ __forceinline__ void gemm_issue_chunk(
    const __nv_bfloat16* __restrict__ Ahi, const __nv_bfloat16* __restrict__ Alo,
    const __nv_bfloat16* __restrict__ Bhi, const __nv_bfloat16* __restrict__ Blo,
    int m0, int n0, int kc, uint32_t sb)
{
    const int tid = threadIdx.x;
    const int k0 = kc * 32;
    #pragma unroll
    for (int it = 0; it < 8; it++) {
        int idx = tid + it * 256;
        int sel = idx >> 10;
        int sub = idx & 1023;
        int r = sub >> 3;
        int cb = sub & 7;
        uint32_t off = (uint32_t)(r * 128 + cb * 16);
        uint32_t sw = off ^ (uint32_t)((r & 7) << 4);
        const __nv_bfloat16* src = sel ? ((cb < 4) ? Bhi : Blo)
                                       : ((cb < 4) ? Ahi : Alo);
        int row = (sel ? n0 : m0) + r;
        size_t g = (size_t)row * C_ + k0 + (cb & 3) * 8;
        cp16(sb + sel * 16384 + sw, src + g);
    }
    cp_commit();
}

__device__ __forceinline__ void gemm_mma(
    const __nv_bfloat16* __restrict__ Ahi, const __nv_bfloat16* __restrict__ Alo,
    const __nv_bfloat16* __restrict__ Bhi, const __nv_bfloat16* __restrict__ Blo,
    int m0, int n0, char* smem, float acc[4][4][4])
{
    const int tid = threadIdx.x;
    const int wid = tid >> 5;
    const int lane = tid & 31;
    const int wm = wid >> 2;
    const int wn = wid & 3;
    const uint32_t sbase = smem_u32(smem);

    #pragma unroll
    for (int mi = 0; mi < 4; mi++)
        #pragma unroll
        for (int nj = 0; nj < 4; nj++)
            #pragma unroll
            for (int e = 0; e < 4; e++) acc[mi][nj][e] = 0.f;

    const int a_row = lane & 15;
    const int a_kh  = lane >> 4;
    const int bg    = lane >> 3;
    const int b_row = ((bg >> 1) << 3) + (lane & 7);
    const int b_kh  = bg & 1;

    gemm_issue_chunk(Ahi, Alo, Bhi, Blo, m0, n0, 0, sbase);

    for (int kc = 0; kc < NCH32_; kc++) {
        if (kc + 1 < NCH32_) {
            gemm_issue_chunk(Ahi, Alo, Bhi, Blo, m0, n0, kc + 1,
                             sbase + ((kc + 1) & 1) * GSTG_);
            cp_wait<1>();
        } else {
            cp_wait<0>();
        }
        __syncthreads();

        const uint32_t st = sbase + (kc & 1) * GSTG_;
        #pragma unroll
        for (int kk = 0; kk < 2; kk++) {
            uint32_t bh[4][2], bl[4][2];
            #pragma unroll
            for (int np = 0; np < 2; np++) {
                int R = wn * 32 + np * 16 + b_row;
                int cbh = kk * 2 + b_kh;
                uint32_t offh = (uint32_t)(R * 128 + cbh * 16);
                uint32_t offl = (uint32_t)(R * 128 + (cbh + 4) * 16);
                uint32_t swm = (uint32_t)((R & 7) << 4);
                ldsm_x4(st + 16384 + (offh ^ swm), &bh[np * 2][0]);
                ldsm_x4(st + 16384 + (offl ^ swm), &bl[np * 2][0]);
            }
            #pragma unroll
            for (int mi = 0; mi < 4; mi++) {
                uint32_t ah[4], al[4];
                int R = wm * 64 + mi * 16 + a_row;
                int cbh = kk * 2 + a_kh;
                uint32_t offh = (uint32_t)(R * 128 + cbh * 16);
                uint32_t offl = (uint32_t)(R * 128 + (cbh + 4) * 16);
                uint32_t swm = (uint32_t)((R & 7) << 4);
                ldsm_x4(st + (offh ^ swm), ah);
                ldsm_x4(st + (offl ^ swm), al);
                #pragma unroll
                for (int nj = 0; nj < 4; nj++) {
                    mma16816(acc[mi][nj], ah, bh[nj]);
                    mma16816(acc[mi][nj], ah, bl[nj]);
                    mma16816(acc[mi][nj], al, bh[nj]);
                }
            }
        }
        __syncthreads();
    }
}

__device__ __forceinline__ void acc_to_smem(
    float acc[4][4][4], char* smem, const float* __restrict__ bias, int n0)
{
    float* Cs = (float*)smem;
    const int wid = threadIdx.x >> 5;
    const int lane = threadIdx.x & 31;
    const int wm = wid >> 2, wn = wid & 3;
    const int r0 = wm * 64 + (lane >> 2);
    const int c0 = wn * 32 + 2 * (lane & 3);
    #pragma unroll
    for (int mi = 0; mi < 4; mi++) {
        #pragma unroll
        for (int nj = 0; nj < 4; nj++) {
            int r = r0 + mi * 16;
            int c = c0 + nj * 8;
            float b0 = __ldg(&bias[n0 + c]);
            float b1 = __ldg(&bias[n0 + c + 1]);
            Cs[r * CS_LD + c]           = acc[mi][nj][0] + b0;
            Cs[r * CS_LD + c + 1]       = acc[mi][nj][1] + b1;
            Cs[(r + 8) * CS_LD + c]     = acc[mi][nj][2] + b0;
            Cs[(r + 8) * CS_LD + c + 1] = acc[mi][nj][3] + b1;
        }
    }
}

// ---------------- QKV GEMM + bias + RoPE + hi/lo split epilogue ------------
__global__ __launch_bounds__(256, 2) void qkv_mma_kernel(
    const float* __restrict__ bq, const float* __restrict__ bk,
    const float* __restrict__ bv)
{
    extern __shared__ __align__(16) char smem[];
    const int z = blockIdx.z;
    const __nv_bfloat16* Whi = g_whi + (size_t)z * C_ * C_;
    const __nv_bfloat16* Wlo = g_wlo + (size_t)z * C_ * C_;
    const float* bias = (z == 0) ? bq : (z == 1) ? bk : bv;

    const int m0 = blockIdx.x * 128;
    const int n0 = blockIdx.y * 128;

    float acc[4][4][4];
    gemm_mma(g_xhi, g_xlo, Whi, Wlo, m0, n0, smem, acc);
    acc_to_smem(acc, smem, bias, n0);
    __syncthreads();

    const float* Cs = (const float*)smem;
    const int tid = threadIdx.x;
    const int b = m0 / T_;
    const int tbase = m0 % T_;

    if (z < 2) {
        __nv_bfloat16* dHi = (z == 0) ? g_qhi : g_khi;
        __nv_bfloat16* dLo = (z == 0) ? g_qlo : g_klo;
        #pragma unroll
        for (int it = 0; it < 32; it++) {
            int p = tid + it * 256;
            int row = p >> 6;
            int q6 = p & 63;
            int hd = q6 >> 5;
            int i = q6 & 31;
            int t = tbase + row;
            int h = (n0 >> 6) + hd;
            float xr = Cs[row * CS_LD + hd * 64 + i];
            float xi = Cs[row * CS_LD + hd * 64 + i + 32];
            float cs = g_cos[t * HALF_ + i];
            float sn = g_sin[t * HALF_ + i];
            float a = xr * cs - xi * sn;
            float c = xr * sn + xi * cs;
            size_t base = ((size_t)(b * H_ + h) * T_ + t) * D_;
            // truncation split (hi exact top bits, lo = rn residual)
            uint32_t ua = __float_as_uint(a), uc = __float_as_uint(c);
            float fa = __uint_as_float(ua & 0xFFFF0000u);
            float fc = __uint_as_float(uc & 0xFFFF0000u);
            dHi[base + i]      = __ushort_as_bfloat16((unsigned short)(ua >> 16));
            dHi[base + i + 32] = __ushort_as_bfloat16((unsigned short)(uc >> 16));
            dLo[base + i]      = __float2bfloat16(a - fa);
            dLo[base + i + 32] = __float2bfloat16(c - fc);
        }
    } else {
        #pragma unroll
        for (int it = 0; it < 16; it++) {
            int e = tid + it * 256;
            int row = e >> 5;
            int col = (e & 31) * 4;
            int hd = col >> 6;
            int d = col & 63;
            int t = tbase + row;
            int h = (n0 >> 6) + hd;
            float4 v4 = *(const float4*)&Cs[row * CS_LD + col];
            uint32_t h0, l0, h1, l1;
            split2(v4.x, v4.y, h0, l0);
            split2(v4.z, v4.w, h1, l1);
            size_t base = ((size_t)(b * H_ + h) * T_ + t) * D_ + d;
            ((uint32_t*)(g_vhi + base))[0] = h0;
            ((uint32_t*)(g_vhi + base))[1] = h1;
            ((uint32_t*)(g_vlo + base))[0] = l0;
            ((uint32_t*)(g_vlo + base))[1] = l1;
        }
    }
}

// ---------------- output projection GEMM -----------------------------------
__global__ __launch_bounds__(256, 2) void proj_mma_kernel(
    const float* __restrict__ bp, float* __restrict__ out)
{
    extern __shared__ __align__(16) char smem[];
    const int m0 = blockIdx.x * 128;
    const int n0 = blockIdx.y * 128;
    const __nv_bfloat16* Whi = g_whi + (size_t)3 * C_ * C_;
    const __nv_bfloat16* Wlo = g_wlo + (size_t)3 * C_ * C_;

    float acc[4][4][4];
    gemm_mma(g_yhi, g_ylo, Whi, Wlo, m0, n0, smem, acc);
    acc_to_smem(acc, smem, bp, n0);
    __syncthreads();

    const float* Cs = (const float*)smem;
    const int tid = threadIdx.x;
    #pragma unroll
    for (int it = 0; it < 16; it++) {
        int e = tid + it * 256;
        int row = e >> 5;
        int col = (e & 31) * 4;
        float4 v4 = *(const float4*)&Cs[row * CS_LD + col];
        *(float4*)&out[(size_t)(m0 + row) * C_ + n0 + col] = v4;
    }
}

// ---------------- attention: 2 independent 4-warp groups per CTA -----------
// grid (T/128, H, B), 256 threads. Group g handles q rows [g*64, g*64+64).
// Per group: 32-key tiles, two 16KB stages at g*32768 + s*16384:
//   K_hi +0 (4KB), K_lo +4096, V_hi +8192, V_lo +12288
#define AG_ 32768
#define ATT_SMEM (2 * AG_)    // 65536

__device__ __forceinline__ void attn_issue_tile32(
    const __nv_bfloat16* __restrict__ Khi, const __nv_bfloat16* __restrict__ Klo,
    const __nv_bfloat16* __restrict__ Vhi, const __nv_bfloat16* __restrict__ Vlo,
    int ti, uint32_t sb, int wg_tid)
{
    #pragma unroll
    for (int it = 0; it < 8; it++) {
        int idx = wg_tid + it * 128;      // 0..1023
        int sel = idx >> 8;               // 0..3
        int sub = idx & 255;
        int r = sub >> 3;                 // 0..31
        int cb = sub & 7;
        uint32_t off = (uint32_t)(r * 128 + cb * 16);
        uint32_t sw = off ^ (uint32_t)((r & 7) << 4);
        size_t g = (size_t)(ti * 32 + r) * D_ + cb * 8;
        const __nv_bfloat16* src = (sel == 0) ? Khi : (sel == 1) ? Klo
                                  : (sel == 2) ? Vhi : Vlo;
        cp16(sb + sel * 4096 + sw, src + g);
    }
    cp_commit();
}

__global__ __launch_bounds__(256, 2) void attn_mma_kernel() {
    extern __shared__ __align__(16) char smem[];
    const uint32_t sbase = smem_u32(smem);
    const int tid = threadIdx.x;
    const int grp = tid >> 7;             // 0..1
    const int wg_tid = tid & 127;
    const int w = wg_tid >> 5;            // warp in group 0..3
    const int lane = tid & 31;
    const int bx = blockIdx.x;
    const int h = blockIdx.y;
    const int b = blockIdx.z;
    const int barid = grp + 1;

    const size_t head = (size_t)(b * H_ + h) * T_ * D_;
    const __nv_bfloat16* Qhi = g_qhi + head;
    const __nv_bfloat16* Qlo = g_qlo + head;
    const __nv_bfloat16* Khi = g_khi + head;
    const __nv_bfloat16* Klo = g_klo + head;
    const __nv_bfloat16* Vhi = g_vhi + head;
    const __nv_bfloat16* Vlo = g_vlo + head;

    const uint32_t gbase = sbase + grp * AG_;
    const int qrow0 = bx * 128 + grp * 64;

    // ---- stage this group's Q (64 x 64 hi/lo) into its region, get frags ----
    #pragma unroll
    for (int it = 0; it < 4; it++) {
        int idx = wg_tid + it * 128;      // 0..511
        int r = idx >> 3;                 // 0..63
        int cb = idx & 7;
        uint32_t off = (uint32_t)(r * 128 + cb * 16);
        uint32_t sw = off ^ (uint32_t)((r & 7) << 4);
        size_t g = (size_t)(qrow0 + r) * D_ + cb * 8;
        *(uint4*)(smem + grp * AG_ + sw)        = *(const uint4*)(Qhi + g);
        *(uint4*)(smem + grp * AG_ + 8192 + sw) = *(const uint4*)(Qlo + g);
    }
    BARG(barid);

    uint32_t qh[4][4], ql[4][4];
    {
        const int a_row = lane & 15;
        const int a_kh = lane >> 4;
        #pragma unroll
        for (int kt = 0; kt < 4; kt++) {
            int R = w * 16 + a_row;
            int cb = kt * 2 + a_kh;
            uint32_t off = (uint32_t)(R * 128 + cb * 16);
            uint32_t sw = off ^ (uint32_t)((R & 7) << 4);
            ldsm_x4(gbase + sw, qh[kt]);
            ldsm_x4(gbase + 8192 + sw, ql[kt]);
        }
    }
    BARG(barid);

    const int q0 = qrow0 + w * 16 + (lane >> 2);
    const int q1 = q0 + 8;
    float m0 = -INFINITY, m1 = -INFINITY, l0 = 0.f, l1 = 0.f;
    float acc_o[8][4];
    #pragma unroll
    for (int j = 0; j < 8; j++)
        #pragma unroll
        for (int e = 0; e < 4; e++) acc_o[j][e] = 0.f;

    const float S2 = 0.125f * 1.44269504088896f;

    const int bg = lane >> 3;
    const int b_row = ((bg >> 1) << 3) + (lane & 7);
    const int b_kh = bg & 1;
    const int l7 = lane & 7;
    const int maskt = 4 * bx + 2 * grp;   // first tile that can cross diagonal
    const int ntiles = maskt + 2;

    attn_issue_tile32(Khi, Klo, Vhi, Vlo, 0, gbase, wg_tid);

    for (int ti = 0; ti < ntiles; ti++) {
        if (ti + 1 < ntiles) {
            attn_issue_tile32(Khi, Klo, Vhi, Vlo, ti + 1,
                              gbase + ((ti + 1) & 1) * 16384, wg_tid);
            cp_wait<1>();
        } else {
            cp_wait<0>();
        }
        BARG(barid);

        const uint32_t st = gbase + (ti & 1) * 16384;

        // ---- S = Q K^T over 32 keys ----
        float acc[4][4];
        #pragma unroll
        for (int j = 0; j < 4; j++)
            #pragma unroll
            for (int e = 0; e < 4; e++) acc[j][e] = 0.f;

        #pragma unroll
        for (int kt = 0; kt < 4; kt++) {
            uint32_t bh[4][2], bl[4][2];
            #pragma unroll
            for (int np = 0; np < 2; np++) {
                int R = np * 16 + b_row;
                int cb = kt * 2 + b_kh;
                uint32_t off = (uint32_t)(R * 128 + cb * 16);
                uint32_t sw = off ^ (uint32_t)((R & 7) << 4);
                ldsm_x4(st + sw, &bh[np * 2][0]);
                ldsm_x4(st + 4096 + sw, &bl[np * 2][0]);
            }
            #pragma unroll
            for (int j = 0; j < 4; j++) {
                mma16816(acc[j], qh[kt], bh[j]);
                mma16816(acc[j], qh[kt], bl[j]);
                mma16816(acc[j], ql[kt], bh[j]);
            }
        }

        // ---- causal mask ----
        if (ti >= maskt) {
            #pragma unroll
            for (int j = 0; j < 4; j++) {
                int s0 = ti * 32 + 8 * j + 2 * (lane & 3);
                if (s0     > q0) acc[j][0] = -INFINITY;
                if (s0 + 1 > q0) acc[j][1] = -INFINITY;
                if (s0     > q1) acc[j][2] = -INFINITY;
                if (s0 + 1 > q1) acc[j][3] = -INFINITY;
            }
        }

        // ---- online softmax ----
        float mt0 = -INFINITY, mt1 = -INFINITY;
        #pragma unroll
        for (int j = 0; j < 4; j++) {
            mt0 = fmaxf(mt0, fmaxf(acc[j][0], acc[j][1]));
            mt1 = fmaxf(mt1, fmaxf(acc[j][2], acc[j][3]));
        }
        mt0 = fmaxf(mt0, __shfl_xor_sync(0xffffffff, mt0, 1));
        mt0 = fmaxf(mt0, __shfl_xor_sync(0xffffffff, mt0, 2));
        mt1 = fmaxf(mt1, __shfl_xor_sync(0xffffffff, mt1, 1));
        mt1 = fmaxf(mt1, __shfl_xor_sync(0xffffffff, mt1, 2));

        float mn0 = fmaxf(m0, mt0);
        float mn1 = fmaxf(m1, mt1);
        float c0 = exp2f((m0 - mn0) * S2);
        float c1 = exp2f((m1 - mn1) * S2);
        l0 *= c0; l1 *= c1;
        #pragma unroll
        for (int j = 0; j < 8; j++) {
            acc_o[j][0] *= c0; acc_o[j][1] *= c0;
            acc_o[j][2] *= c1; acc_o[j][3] *= c1;
        }
        float fm0 = mn0 * S2, fm1 = mn1 * S2;
        #pragma unroll
        for (int j = 0; j < 4; j++) {
            float p0 = exp2f(acc[j][0] * S2 - fm0);
            float p1 = exp2f(acc[j][1] * S2 - fm0);
            float p2 = exp2f(acc[j][2] * S2 - fm1);
            float p3 = exp2f(acc[j][3] * S2 - fm1);
            l0 += p0 + p1;
            l1 += p2 + p3;
            acc[j][0] = p0; acc[j][1] = p1; acc[j][2] = p2; acc[j][3] = p3;
        }
        m0 = mn0; m1 = mn1;

        // ---- O += P V over 32 keys ----
        #pragma unroll
        for (int kt = 0; kt < 2; kt++) {
            uint32_t ph[4], pl[4];
            split2(acc[2 * kt][0],     acc[2 * kt][1],     ph[0], pl[0]);
            split2(acc[2 * kt][2],     acc[2 * kt][3],     ph[1], pl[1]);
            split2(acc[2 * kt + 1][0], acc[2 * kt + 1][1], ph[2], pl[2]);
            split2(acc[2 * kt + 1][2], acc[2 * kt + 1][3], ph[3], pl[3]);
            #pragma unroll
            for (int np = 0; np < 4; np++) {
                int srow = kt * 16 + ((bg & 1) << 3) + l7;
                int dcol = np * 16 + ((bg >> 1) << 3);
                uint32_t off = (uint32_t)(srow * 128 + dcol * 2);
                uint32_t sw = off ^ (uint32_t)((srow & 7) << 4);
                uint32_t vh[4], vl[4];
                ldsm_x4_trans(st + 8192 + sw, vh);
                ldsm_x4_trans(st + 12288 + sw, vl);
                mma16816(acc_o[2 * np],     ph, &vh[0]);
                mma16816(acc_o[2 * np],     ph, &vl[0]);
                mma16816(acc_o[2 * np],     pl, &vh[0]);
                mma16816(acc_o[2 * np + 1], ph, &vh[2]);
                mma16816(acc_o[2 * np + 1], ph, &vl[2]);
                mma16816(acc_o[2 * np + 1], pl, &vh[2]);
            }
        }
        BARG(barid);
    }

    // ---- finalize ----
    l0 += __shfl_xor_sync(0xffffffff, l0, 1);
    l0 += __shfl_xor_sync(0xffffffff, l0, 2);
    l1 += __shfl_xor_sync(0xffffffff, l1, 1);
    l1 += __shfl_xor_sync(0xffffffff, l1, 2);
    float inv0 = 1.f / l0;
    float inv1 = 1.f / l1;

    const size_t row0 = (size_t)(b * T_ + q0) * C_ + h * 64;
    const size_t row1 = (size_t)(b * T_ + q1) * C_ + h * 64;
    #pragma unroll
    for (int j = 0; j < 8; j++) {
        int d = 8 * j + 2 * (lane & 3);
        uint32_t hi, lo;
        split2(acc_o[j][0] * inv0, acc_o[j][1] * inv0, hi, lo);
        *(uint32_t*)(g_yhi + row0 + d) = hi;
        *(uint32_t*)(g_ylo + row0 + d) = lo;
        split2(acc_o[j][2] * inv1, acc_o[j][3] * inv1, hi, lo);
        *(uint32_t*)(g_yhi + row1 + d) = hi;
        *(uint32_t*)(g_ylo + row1 + d) = lo;
    }
}

// ---------------- launch ---------------------------------------------------
extern "C" void kernel_launch(void* const* d_in, const int* in_sizes, int n_in,
                              void* d_out, int out_size)
{
    const float* x  = (const float*)d_in[0];
    const float* wq = (const float*)d_in[1];
    const float* bq = (const float*)d_in[2];
    const float* wk = (const float*)d_in[3];
    const float* bk = (const float*)d_in[4];
    const float* wv = (const float*)d_in[5];
    const float* bv = (const float*)d_in[6];
    const float* wp = (const float*)d_in[7];
    const float* bp = (const float*)d_in[8];
    float* out = (float*)d_out;

    static bool attr_done = false;
    if (!attr_done) {
        cudaFuncSetAttribute(qkv_mma_kernel,
                             cudaFuncAttributeMaxDynamicSharedMemorySize, SMEM_BYTES);
        cudaFuncSetAttribute(proj_mma_kernel,
                             cudaFuncAttributeMaxDynamicSharedMemorySize, SMEM_BYTES);
        cudaFuncSetAttribute(attn_mma_kernel,
                             cudaFuncAttributeMaxDynamicSharedMemorySize, ATT_SMEM);
        attr_done = true;
    }

    rope_init_kernel<<<(T_ * HALF_ + 255) / 256, 256>>>();

    const int nsplit = M_ * C_ / 4 + 4 * (C_ * C_ / 4);
    split_all_kernel<<<(nsplit + 255) / 256, 256>>>(x, wq, wk, wv, wp);

    qkv_mma_kernel<<<dim3(M_ / 128, C_ / 128, 3), 256, SMEM_BYTES>>>(bq, bk, bv);
    attn_mma_kernel<<<dim3(T_ / 128, H_, B_), 256, ATT_SMEM>>>();
    proj_mma_kernel<<<dim3(M_ / 128, C_ / 128), 256, SMEM_BYTES>>>(bp, out);
}